// round 15
// baseline (speedup 1.0000x reference)
#include <cuda_runtime.h>
#include <math.h>
#include <stdint.h>

#define D_EMBED 512
#define NHEAD   8
#define DH      64
#define DFF     2048
#define BATCH   2
#define SEQ     4096
#define NROWS   (BATCH*SEQ)   // 8192

#if defined(__CUDA_ARCH__)
# if defined(__CUDA_ARCH_HAS_FEATURE__)
#  if __CUDA_ARCH_HAS_FEATURE__(SM103_ALL)
#   define HAS_TC 1
#  endif
# endif
# if !defined(HAS_TC) && defined(__CUDA_ARCH_SPECIFIC__)
#  define HAS_TC 1
# endif
#endif
#ifndef HAS_TC
# define HAS_TC 0
#endif

// ---------------- scratch ------------------------------------------------------
__device__ float g_q[BATCH*NHEAD*SEQ*DH];
__device__ float g_k[BATCH*NHEAD*SEQ*DH];
__device__ float g_v[BATCH*NHEAD*SEQ*DH];
__device__ float g_ctx[NROWS*D_EMBED];
__device__ float g_ff[(size_t)NROWS*DFF];
__device__ float g_res1[NROWS*D_EMBED];
__device__ float g_h[NROWS*D_EMBED];
__device__ float g_hs[NROWS*D_EMBED];
__device__ float g_xs[NROWS*D_EMBED];
__device__ float g_res2[NROWS*D_EMBED];
__device__ float g_wqkvt[3*D_EMBED*D_EMBED];
__device__ float g_wot[D_EMBED*D_EMBED];
__device__ float g_w1t[DFF*D_EMBED];
__device__ float g_w2t[D_EMBED*DFF];

// ---------------- helpers ------------------------------------------------------
__device__ __forceinline__ float gelu_f(float x) {
    return 0.5f * x * (1.0f + erff(x * 0.70710678118654752f));
}
__device__ __forceinline__ uint32_t smem_u32(const void* p) {
    uint32_t a;
    asm("{ .reg .u64 t; cvta.to.shared.u64 t, %1; cvt.u32.u64 %0, t; }" : "=r"(a) : "l"(p));
    return a;
}
__device__ __forceinline__ int swz_fi(int r, int j) {
    int g = j >> 2;
    return r * 32 + ((g ^ (r & 7)) << 2) + (j & 3);
}
__device__ __forceinline__ float ld_swz(const float* Wt, int NC, int n, int k) {
    int blk = (n >> 8) * NC + (k >> 5);
    int off = (n & 255) * 128 + (k & 31) * 4;
    int sw = off ^ ((off >> 3) & 0x70);
    return *(const float*)((const char*)(Wt + (size_t)blk * 8192) + sw);
}

#if HAS_TC
__device__ __forceinline__ uint32_t elect_one_pred() {
    uint32_t pred;
    asm volatile("{\n\t.reg .pred p;\n\telect.sync _|p, 0xFFFFFFFF;\n\t"
                 "selp.b32 %0, 1, 0, p;\n\t}" : "=r"(pred));
    return pred;
}
#define MBAR_INIT(a, n) asm volatile("mbarrier.init.shared.b64 [%0], %1;" :: "r"(a), "r"(n) : "memory")
#define MBAR_EXPECT_TX(a, bytes) \
    asm volatile("mbarrier.arrive.expect_tx.shared.b64 _, [%0], %1;" :: "r"(a), "r"(bytes) : "memory")
#define MBAR_WAIT(a, par) do { \
    uint32_t _m = (a), _p = (par), _d; \
    asm volatile("{\n\t.reg .pred p;\n\t" \
        "mbarrier.try_wait.parity.acquire.cta.shared::cta.b64 p, [%1], %2;\n\t" \
        "selp.b32 %0, 1, 0, p;\n\t}" : "=r"(_d) : "r"(_m), "r"(_p) : "memory"); \
    if (!_d) { asm volatile("{\n\t.reg .pred P1;\n\tWL_%=:\n\t" \
        "mbarrier.try_wait.parity.acquire.cta.shared::cta.b64 P1, [%0], %1, 0x989680;\n\t" \
        "@P1 bra.uni WD_%=;\n\tbra.uni WL_%=;\n\tWD_%=:\n\t}" \
        :: "r"(_m), "r"(_p) : "memory"); } \
} while (0)
#define BULK_CP(dst, src, sz, mb) \
    asm volatile("cp.async.bulk.shared::cluster.global.mbarrier::complete_tx::bytes [%0], [%1], %2, [%3];" \
        :: "r"(dst), "l"(src), "r"(sz), "r"(mb) : "memory")

#define TC_ALLOC(sa, n)   asm volatile("tcgen05.alloc.cta_group::1.sync.aligned.shared::cta.b32 [%0], %1;" :: "r"(sa), "r"(n) : "memory")
#define TC_DEALLOC(t, n)  asm volatile("tcgen05.dealloc.cta_group::1.sync.aligned.b32 %0, %1;" :: "r"(t), "r"(n))
#define TC_COMMIT(mb)     asm volatile("tcgen05.commit.cta_group::1.mbarrier::arrive::one.shared::cluster.b64 [%0];" :: "r"(mb) : "memory")
#define TC_FENCE_AFTER()  asm volatile("tcgen05.fence::after_thread_sync;" ::: "memory")
#define TC_FENCE_BEFORE() asm volatile("tcgen05.fence::before_thread_sync;" ::: "memory")
#define TC_WAIT_LD()      asm volatile("tcgen05.wait::ld.sync.aligned;" ::: "memory")
#define TC_WAIT_ST()      asm volatile("tcgen05.wait::st.sync.aligned;" ::: "memory")
#define FENCE_ASYNC()     asm volatile("fence.proxy.async.shared::cta;" ::: "memory")

#define TC_LD_X32(r, ta) \
    asm volatile("tcgen05.ld.sync.aligned.32x32b.x32.b32 " \
        "{%0, %1, %2, %3, %4, %5, %6, %7, %8, %9, %10, %11, %12, %13, %14, %15, " \
        " %16, %17, %18, %19, %20, %21, %22, %23, %24, %25, %26, %27, %28, %29, %30, %31}, [%32];" \
        : "=r"((r)[0]), "=r"((r)[1]), "=r"((r)[2]), "=r"((r)[3]), \
          "=r"((r)[4]), "=r"((r)[5]), "=r"((r)[6]), "=r"((r)[7]), \
          "=r"((r)[8]), "=r"((r)[9]), "=r"((r)[10]), "=r"((r)[11]), \
          "=r"((r)[12]), "=r"((r)[13]), "=r"((r)[14]), "=r"((r)[15]), \
          "=r"((r)[16]), "=r"((r)[17]), "=r"((r)[18]), "=r"((r)[19]), \
          "=r"((r)[20]), "=r"((r)[21]), "=r"((r)[22]), "=r"((r)[23]), \
          "=r"((r)[24]), "=r"((r)[25]), "=r"((r)[26]), "=r"((r)[27]), \
          "=r"((r)[28]), "=r"((r)[29]), "=r"((r)[30]), "=r"((r)[31]) \
        : "r"(ta))

#define TC_ST_X32(ta, r) \
    asm volatile("tcgen05.st.sync.aligned.32x32b.x32.b32 [%0], " \
        "{%1, %2, %3, %4, %5, %6, %7, %8, %9, %10, %11, %12, %13, %14, %15, %16, " \
        " %17, %18, %19, %20, %21, %22, %23, %24, %25, %26, %27, %28, %29, %30, %31, %32};" \
        :: "r"(ta), \
           "r"((r)[0]), "r"((r)[1]), "r"((r)[2]), "r"((r)[3]), \
           "r"((r)[4]), "r"((r)[5]), "r"((r)[6]), "r"((r)[7]), \
           "r"((r)[8]), "r"((r)[9]), "r"((r)[10]), "r"((r)[11]), \
           "r"((r)[12]), "r"((r)[13]), "r"((r)[14]), "r"((r)[15]), \
           "r"((r)[16]), "r"((r)[17]), "r"((r)[18]), "r"((r)[19]), \
           "r"((r)[20]), "r"((r)[21]), "r"((r)[22]), "r"((r)[23]), \
           "r"((r)[24]), "r"((r)[25]), "r"((r)[26]), "r"((r)[27]), \
           "r"((r)[28]), "r"((r)[29]), "r"((r)[30]), "r"((r)[31]) \
        : "memory")

#define TC_MMA_TF32(dt, ad, bd, id, en) do { \
    uint32_t _e = (en) ? 1u : 0u; \
    asm volatile("{\n\t.reg .pred p;\n\tsetp.ne.u32 p, %5, 0;\n\t" \
        "tcgen05.mma.cta_group::1.kind::tf32 [%0], %1, %2, %3, {%4, %4, %4, %4}, p;\n\t}" \
        :: "r"(dt), "l"(ad), "l"(bd), "r"(id), "r"(0u), "r"(_e) : "memory"); \
} while (0)

#define TC_MMA_TF32_TS(dt, at, bd, id, en) do { \
    uint32_t _e = (en) ? 1u : 0u; \
    asm volatile("{\n\t.reg .pred p;\n\tsetp.ne.u32 p, %5, 0;\n\t" \
        "tcgen05.mma.cta_group::1.kind::tf32 [%0], [%1], %2, %3, {%4, %4, %4, %4}, p;\n\t}" \
        :: "r"(dt), "r"(at), "l"(bd), "r"(id), "r"(0u), "r"(_e) : "memory"); \
} while (0)

__device__ __forceinline__ uint64_t make_desc(uint32_t addr) {
    return ((uint64_t)2 << 61) | ((uint64_t)1 << 46) | ((uint64_t)64 << 32) |
           ((uint64_t)1 << 16) | (uint64_t)((addr >> 4) & 0x3FFF);
}
#define IDESC_G   ((1u << 4) | (2u << 7) | (2u << 10) | (32u << 17) | (8u << 24))  // M128 N256
#define IDESC_128 ((1u << 4) | (2u << 7) | (2u << 10) | (16u << 17) | (8u << 24))  // M128 N128
#define IDESC_PV  ((1u << 4) | (2u << 7) | (2u << 10) | (8u  << 17) | (8u << 24))  // M128 N64
#endif // HAS_TC

// ---------------- weight pre-swizzle -------------------------------------------
__global__ __launch_bounds__(256)
void prep_all(const float* __restrict__ Wq, const float* __restrict__ Wk,
              const float* __restrict__ Wv, const float* __restrict__ Wo,
              const float* __restrict__ W1, const float* __restrict__ W2,
              float* __restrict__ wqkvt, float* __restrict__ wot,
              float* __restrict__ w1t, float* __restrict__ w2t)
{
    int id = blockIdx.x;
    const float* src; float* dst; int Kd, Nd, lb;
    if      (id < 1024) { src = Wq; dst = wqkvt;            Kd = 512;  Nd = 512;  lb = id; }
    else if (id < 2048) { src = Wk; dst = wqkvt + 512*512;  Kd = 512;  Nd = 512;  lb = id - 1024; }
    else if (id < 3072) { src = Wv; dst = wqkvt + 2*512*512;Kd = 512;  Nd = 512;  lb = id - 2048; }
    else if (id < 4096) { src = Wo; dst = wot;              Kd = 512;  Nd = 512;  lb = id - 3072; }
    else if (id < 8192) { src = W1; dst = w1t;              Kd = 512;  Nd = 2048; lb = id - 4096; }
    else                { src = W2; dst = w2t;              Kd = 2048; Nd = 512;  lb = id - 8192; }
    int e = lb * 256 + threadIdx.x;
    int k = e / Nd, n = e % Nd;
    float v = src[e];
    int NC = Kd >> 5;
    int blk = (n >> 8) * NC + (k >> 5);
    int off = (n & 255) * 128 + (k & 31) * 4;
    int sw = off ^ ((off >> 3) & 0x70);
    *(float*)((char*)(dst + (size_t)blk * 8192) + sw) = v;
}

// ---------------- x row-major -> A-swizzled ------------------------------------
__global__ __launch_bounds__(256)
void swz_a(const float* __restrict__ src, float* __restrict__ dst)
{
    int idx = blockIdx.x * 256 + threadIdx.x;
    int e = idx * 4;
    int m = e >> 9, k = e & 511;
    float4 v = *(const float4*)(src + (size_t)e);
    int blk = (m >> 7) * 16 + (k >> 5);
    *(float4*)(dst + (size_t)blk * 4096 + swz_fi(m & 127, k & 31)) = v;
}

// ---------------- GEMM (R13 config) ---------------------------------------------
#define GEMM_SMEM_S2  98304
#define GEMM_SMEM_S3  147456
template<int MODE, int STAGES>
__global__ __launch_bounds__(256, 2)
void gemmT(const float* __restrict__ A, const float* __restrict__ Wt,
           const float* __restrict__ bias0, const float* __restrict__ bias1,
           const float* __restrict__ bias2, const float* __restrict__ resid,
           float* __restrict__ out0, float* __restrict__ out1, float* __restrict__ out2,
           int N, int K)
{
    extern __shared__ __align__(1024) float sm[];
    const int tid = threadIdx.x, wid = tid >> 5, lane = tid & 31;
    const int n0 = blockIdx.x * 256, m0 = blockIdx.y * 128;
    const int NC = K >> 5;

#if HAS_TC
    __shared__ uint32_t s_tptr;
    __shared__ unsigned long long s_mb[6];
    const uint32_t smb = smem_u32(sm);
    const uint32_t BOF = STAGES * 16384u;

    if (wid == 0) TC_ALLOC(smem_u32(&s_tptr), 256);
    if (tid == 0) {
        #pragma unroll
        for (int i = 0; i < 6; ++i) MBAR_INIT(smem_u32(&s_mb[i]), 1);
    }
    __syncthreads();
    const uint32_t tmem = s_tptr;
    uint32_t mbB[3] = {smem_u32(&s_mb[0]), smem_u32(&s_mb[1]), smem_u32(&s_mb[2])};
    uint32_t mbM[3] = {smem_u32(&s_mb[3]), smem_u32(&s_mb[4]), smem_u32(&s_mb[5])};

    if (tid == 0) {
        int cB[3] = {0, 0, 0}, cM[3] = {0, 0, 0};
        const size_t ablk = (size_t)blockIdx.y * NC;
        const size_t bblk = (size_t)blockIdx.x * NC;
        #pragma unroll
        for (int s = 0; s < STAGES; ++s) {
            MBAR_EXPECT_TX(mbB[s], 49152u);
            BULK_CP(smb + s * 16384, (const void*)(A + (ablk + s) * 4096), 16384u, mbB[s]);
            BULK_CP(smb + BOF + s * 32768, (const void*)(Wt + (bblk + s) * 8192), 32768u, mbB[s]);
        }
        for (int s = 0; s < NC; ++s) {
            const int buf = s % STAGES;
            MBAR_WAIT(mbB[buf], cB[buf] & 1); cB[buf]++;
            uint64_t ad = make_desc(smb + buf * 16384);
            uint64_t bd = make_desc(smb + BOF + buf * 32768);
            #pragma unroll
            for (int s2 = 0; s2 < 4; ++s2)
                TC_MMA_TF32(tmem, ad + 2 * s2, bd + 2 * s2, IDESC_G, (s > 0) || (s2 > 0));
            TC_COMMIT(mbM[buf]);
            if (s + STAGES < NC) {
                MBAR_WAIT(mbM[buf], cM[buf] & 1); cM[buf]++;
                MBAR_EXPECT_TX(mbB[buf], 49152u);
                BULK_CP(smb + buf * 16384, (const void*)(A + (ablk + s + STAGES) * 4096),
                        16384u, mbB[buf]);
                BULK_CP(smb + BOF + buf * 32768, (const void*)(Wt + (bblk + s + STAGES) * 8192),
                        32768u, mbB[buf]);
            }
        }
        #pragma unroll
        for (int b2 = 0; b2 < STAGES; ++b2) {
            int cnt = (NC - b2 + STAGES - 1) / STAGES;
            if (cnt > cM[b2]) MBAR_WAIT(mbM[b2], (cnt - 1) & 1);
        }
    }
    __syncthreads();
    TC_FENCE_AFTER();

    const int sp = wid & 3, chh = wid >> 2;
    for (int cg = 0; cg < 4; ++cg) {
        uint32_t r[32];
        TC_LD_X32(r, tmem + cg * 64 + chh * 32);
        TC_WAIT_LD();
        const int row = sp * 32 + lane;
        #pragma unroll
        for (int j = 0; j < 32; ++j) sm[row * 65 + chh * 32 + j] = __uint_as_float(r[j]);
        __syncthreads();

        const int nb = n0 + cg * 64;
        if (MODE == 0) {
            const int which = nb >> 9;
            const int hh = (nb >> 6) & 7;
            const int b_ = m0 >> 12;
            const int tile = (m0 & 4095) >> 7;
            const size_t tbase = ((size_t)(b_ * NHEAD + hh) * (SEQ / 128) + tile) * 8192;
            if (which < 2) {
                const int r2 = tid & 127, sel = tid >> 7;
                const float* bp = which ? bias1 : bias0;
                float* outw = which ? out1 : out0;
                const float scale = which ? 1.f : 0.125f;
                const float* src = &sm[r2 * 65 + sel * 32];
                float vv[32];
                #pragma unroll
                for (int j = 0; j < 32; ++j)
                    vv[j] = (src[j] + bp[(nb & 511) + sel * 32 + j]) * scale;
                float* dstb = outw + tbase + sel * 4096 + r2 * 32;
                #pragma unroll
                for (int g = 0; g < 8; ++g)
                    *(float4*)(dstb + ((g ^ (r2 & 7)) << 2)) =
                        make_float4(vv[g * 4], vv[g * 4 + 1], vv[g * 4 + 2], vv[g * 4 + 3]);
            } else {
                const int dloc = tid & 63, kg = tid >> 6;
                const float bia = bias2[(nb & 511) + dloc];
                float vv[32];
                #pragma unroll
                for (int i = 0; i < 32; ++i)
                    vv[i] = sm[(kg * 32 + i) * 65 + dloc] + bia;
                float* dstb = out2 + tbase + kg * 2048 + dloc * 32;
                #pragma unroll
                for (int g = 0; g < 8; ++g)
                    *(float4*)(dstb + ((g ^ (dloc & 7)) << 2)) =
                        make_float4(vv[g * 4], vv[g * 4 + 1], vv[g * 4 + 2], vv[g * 4 + 3]);
            }
        } else if (MODE == 2) {
            const int r2 = tid & 127, sel = tid >> 7;
            const int m = m0 + r2;
            const int n = nb + sel * 32;
            const float* src = &sm[r2 * 65 + sel * 32];
            float* dst = out0 + (size_t)m * N + n;
            const float* rs = resid + (size_t)m * N + n;
            #pragma unroll
            for (int g = 0; g < 8; ++g) {
                float4 b4 = *(const float4*)(bias0 + n + g * 4);
                float4 r4 = *(const float4*)(rs + g * 4);
                *(float4*)(dst + g * 4) = make_float4(
                    src[g * 4 + 0] + b4.x + r4.x, src[g * 4 + 1] + b4.y + r4.y,
                    src[g * 4 + 2] + b4.z + r4.z, src[g * 4 + 3] + b4.w + r4.w);
            }
        } else {
            const int r2 = tid & 127, sel = tid >> 7;
            const int n = nb + sel * 32;
            const float* src = &sm[r2 * 65 + sel * 32];
            float vv[32];
            #pragma unroll
            for (int j = 0; j < 32; ++j) vv[j] = gelu_f(src[j] + bias0[n + j]);
            float* dstb = out0 + ((size_t)(m0 >> 7) * (DFF / 32) + (n >> 5)) * 4096 + r2 * 32;
            #pragma unroll
            for (int g = 0; g < 8; ++g)
                *(float4*)(dstb + ((g ^ (r2 & 7)) << 2)) =
                    make_float4(vv[g * 4], vv[g * 4 + 1], vv[g * 4 + 2], vv[g * 4 + 3]);
        }
        __syncthreads();
    }
    if (wid == 0) TC_DEALLOC(tmem, 256);

#else
    for (int e = tid; e < 128 * 256; e += 256) {
        int mr = e & 127, nc = e >> 7;
        int m = m0 + mr, n = n0 + nc;
        float acc = 0.f;
        for (int k = 0; k < K; ++k) {
            float a = A[((size_t)(m >> 7) * NC + (k >> 5)) * 4096 + swz_fi(m & 127, k & 31)];
            acc += a * ld_swz(Wt, NC, n, k);
        }
        if (MODE == 0) {
            int which = n >> 9, hh = (n >> 6) & 7;
            int b_ = m >> 12, l = m & (SEQ - 1);
            size_t tbase = ((size_t)(b_ * NHEAD + hh) * (SEQ / 128) + (l >> 7)) * 8192;
            if (which < 2) {
                const float* bp = which ? bias1 : bias0;
                float* outw = which ? out1 : out0;
                float val = (acc + bp[n & 511]) * (which ? 1.f : 0.125f);
                outw[tbase + ((n >> 5) & 1) * 4096 + swz_fi(l & 127, n & 31)] = val;
            } else {
                out2[tbase + ((l & 127) >> 5) * 2048 + swz_fi(n & 63, l & 31)] = acc + bias2[n & 511];
            }
        } else if (MODE == 2) {
            out0[(size_t)m * N + n] = acc + bias0[n] + resid[(size_t)m * N + n];
        } else {
            out0[((size_t)(m >> 7) * (DFF / 32) + (n >> 5)) * 4096 + swz_fi(m & 127, n & 31)] =
                gelu_f(acc + bias0[n]);
        }
    }
#endif
}

// ---------------- attention: BQ=128, Q in TMEM, 2 CTAs/SM -----------------------
#define ATTN_SMEM 101376

__global__ __launch_bounds__(256, 2)
void attn_k(const float* __restrict__ q, const float* __restrict__ k,
            const float* __restrict__ v, const int* __restrict__ mask,
            float* __restrict__ ctx)
{
    extern __shared__ __align__(1024) float sm[];
    const int qt = blockIdx.x, h = blockIdx.y, b = blockIdx.z;
    const int tid = threadIdx.x;
    const size_t tb = (size_t)(b * NHEAD + h) * (SEQ / 128);

#if HAS_TC
    float* Ks  = sm;                  // 2 x 8192 (slot0 stages Q first)
    float* Vs  = sm + 16384;          // 8192
    float* lpart = sm + 24576;        // 256
    int*   Msm = (int*)(sm + 24832);  // [4][128]

    __shared__ uint32_t s_tptr;
    __shared__ unsigned long long s_mb[6];   // Q K0 K1 V S O
    const int wid = tid >> 5, lane = tid & 31;
    const int sp = wid & 3, chh = wid >> 2;
    const int NT = SEQ / 128;

    if (wid == 0) TC_ALLOC(smem_u32(&s_tptr), 256);
    if (tid == 0) {
        #pragma unroll
        for (int i = 0; i < 6; ++i) MBAR_INIT(smem_u32(&s_mb[i]), 1);
    }
    __syncthreads();
    const uint32_t tmem = s_tptr;
    const uint32_t mbQ = smem_u32(&s_mb[0]);
    uint32_t mbK[2] = {smem_u32(&s_mb[1]), smem_u32(&s_mb[2])};
    const uint32_t mbV = smem_u32(&s_mb[3]);
    const uint32_t mbS = smem_u32(&s_mb[4]);
    const uint32_t mbO = smem_u32(&s_mb[5]);
    const uint32_t S_T = tmem, O_T = tmem + 128, Q_T = tmem + 192;

    #define ISSUE_QK(kbuf) do { \
        uint64_t kd = make_desc(smem_u32(Ks + (kbuf) * 8192)); \
        _Pragma("unroll") \
        for (int c = 0; c < 2; ++c) \
            _Pragma("unroll") \
            for (int s = 0; s < 4; ++s) \
                TC_MMA_TF32_TS(S_T, Q_T + (c * 4 + s) * 8, kd + c * 1024 + 2 * s, \
                               IDESC_128, (c > 0) || (s > 0)); \
        TC_COMMIT(mbS); \
    } while (0)

    #define ISSUE_PV(t) do { \
        _Pragma("unroll") \
        for (int cc = 0; cc < 4; ++cc) { \
            uint64_t vd = make_desc(smem_u32(Vs + cc * 2048)); \
            _Pragma("unroll") \
            for (int s = 0; s < 4; ++s) \
                TC_MMA_TF32_TS(O_T, S_T + cc * 32 + s * 8, vd + 2 * s, IDESC_PV, \
                               ((t) > 0) || (cc > 0) || (s > 0)); \
        } \
        TC_COMMIT(mbO); \
    } while (0)

    #define SOFTMAX(tslot, lsum) do { \
        uint32_t ra[32], rb[32]; \
        TC_LD_X32(ra, S_T + chh * 64); \
        TC_WAIT_LD(); \
        TC_LD_X32(rb, S_T + chh * 64 + 32); \
        const int* mrow = &Msm[(tslot) * 128 + chh * 64]; \
        _Pragma("unroll") \
        for (int j = 0; j < 32; ++j) { \
            float s = __uint_as_float(ra[j]); \
            s = mrow[j] ? s : -1e9f; \
            float p = __expf(fminf(s, 60.f)); \
            (lsum) += p; \
            ra[j] = __float_as_uint(p); \
        } \
        TC_WAIT_LD(); \
        TC_ST_X32(S_T + chh * 64, ra); \
        _Pragma("unroll") \
        for (int j = 0; j < 32; ++j) { \
            float s = __uint_as_float(rb[j]); \
            s = mrow[32 + j] ? s : -1e9f; \
            float p = __expf(fminf(s, 60.f)); \
            (lsum) += p; \
            rb[j] = __float_as_uint(p); \
        } \
        TC_ST_X32(S_T + chh * 64 + 32, rb); \
        TC_WAIT_ST(); \
        TC_FENCE_BEFORE(); \
    } while (0)

    // ---- prologue: Q -> K-slot0, K(0) -> slot1, V(0) ----
    // K(j) slot assignment: slot = 1 - (j & 1)   (K0->1, K1->0, K2->1, ...)
    if (tid == 0) {
        MBAR_EXPECT_TX(mbQ, 32768u);
        BULK_CP(smem_u32(Ks), (const void*)(q + (tb + qt) * 8192), 32768u, mbQ);
        MBAR_EXPECT_TX(mbK[1], 32768u);
        BULK_CP(smem_u32(Ks + 8192), (const void*)(k + tb * 8192), 32768u, mbK[1]);
        MBAR_EXPECT_TX(mbV, 32768u);
        BULK_CP(smem_u32(Vs), (const void*)(v + tb * 8192), 32768u, mbV);
    }
    if (tid < 128) {
        Msm[tid] = mask[b * SEQ + tid];
        Msm[128 + tid] = mask[b * SEQ + 128 + tid];
    }
    MBAR_WAIT(mbQ, 0);
    if (wid < 4) {
        const int row = wid * 32 + lane;
        #pragma unroll
        for (int cchunk = 0; cchunk < 2; ++cchunk) {
            uint32_t qr[32];
            const float* base = Ks + cchunk * 4096 + row * 32;
            #pragma unroll
            for (int g = 0; g < 8; ++g) {
                float4 f = *(const float4*)(base + ((g ^ (row & 7)) << 2));
                qr[g * 4 + 0] = __float_as_uint(f.x);
                qr[g * 4 + 1] = __float_as_uint(f.y);
                qr[g * 4 + 2] = __float_as_uint(f.z);
                qr[g * 4 + 3] = __float_as_uint(f.w);
            }
            TC_ST_X32(Q_T + cchunk * 32, qr);
        }
        TC_WAIT_ST();
    }
    TC_FENCE_BEFORE();
    __syncthreads();

    int cK[2] = {0, 0}, cV = 0;
    if (tid == 0) {
        TC_FENCE_AFTER();
        MBAR_WAIT(mbK[1], 0); cK[1] = 1;
        ISSUE_QK(1);
        if (1 < NT) {
            MBAR_EXPECT_TX(mbK[0], 32768u);
            BULK_CP(smem_u32(Ks), (const void*)(k + (tb + 1) * 8192), 32768u, mbK[0]);
        }
    }

    float lsum = 0.f;

    for (int t = 0; t < NT; ++t) {
        MBAR_WAIT(mbS, t & 1);
        TC_FENCE_AFTER();
        SOFTMAX((t & 3), lsum);
        __syncthreads();
        if (tid == 0) {
            TC_FENCE_AFTER();
            MBAR_WAIT(mbV, cV & 1); cV++;
            ISSUE_PV(t);
            MBAR_WAIT(mbO, t & 1);
            if (t + 1 < NT) {
                MBAR_EXPECT_TX(mbV, 32768u);
                BULK_CP(smem_u32(Vs), (const void*)(v + (tb + t + 1) * 8192), 32768u, mbV);
                const int kb = t & 1;            // slot of K(t+1) = 1 - ((t+1)&1) = t&1
                MBAR_WAIT(mbK[kb], cK[kb] & 1); cK[kb]++;
                ISSUE_QK(kb);
                if (t + 2 < NT) {
                    const int kb2 = 1 - kb;      // slot of K(t+2)
                    MBAR_EXPECT_TX(mbK[kb2], 32768u);
                    BULK_CP(smem_u32(Ks + kb2 * 8192), (const void*)(k + (tb + t + 2) * 8192),
                            32768u, mbK[kb2]);
                }
            }
        }
        if (t + 2 < NT && tid < 128)
            Msm[((t + 2) & 3) * 128 + tid] = mask[b * SEQ + (t + 2) * 128 + tid];
        __syncthreads();
    }

    // ---- combine l, read O, normalize, store ctx (A-swizzled layout) ----
    const int rr = sp * 32 + lane;
    lpart[chh * 128 + rr] = lsum;
    __syncthreads();
    float linv = 1.f / (lpart[rr] + lpart[128 + rr]);

    TC_FENCE_AFTER();
    uint32_t ro[32];
    TC_LD_X32(ro, O_T + chh * 32);
    TC_WAIT_LD();
    float vv[32];
    #pragma unroll
    for (int j = 0; j < 32; ++j) vv[j] = __uint_as_float(ro[j]) * linv;
    float* dstb = ctx + ((size_t)(b * (SEQ / 128) + qt) * (D_EMBED / 32) + h * 2 + chh) * 4096
                      + rr * 32;
    #pragma unroll
    for (int g = 0; g < 8; ++g)
        *(float4*)(dstb + ((g ^ (rr & 7)) << 2)) =
            make_float4(vv[g * 4], vv[g * 4 + 1], vv[g * 4 + 2], vv[g * 4 + 3]);
    __syncthreads();
    if (wid == 0) TC_DEALLOC(tmem, 256);
    #undef ISSUE_QK
    #undef ISSUE_PV
    #undef SOFTMAX

#else
    // naive correct fallback (never runs on sm_103a HW)
    if (tid >= 128) return;
    const int rr = tid;
    const float* qb2 = q + (tb + qt) * 8192;
    float qv[64], o[64];
    #pragma unroll
    for (int d = 0; d < 64; ++d) {
        qv[d] = qb2[(d >> 5) * 4096 + swz_fi(rr, d & 31)];
        o[d] = 0.f;
    }
    float lsum = 0.f;
    for (int l = 0; l < SEQ; ++l) {
        int kt = l >> 7, r = l & 127;
        const float* kb2 = k + (tb + kt) * 8192;
        float s = 0.f;
        for (int d = 0; d < 64; ++d) s += qv[d] * kb2[(d >> 5) * 4096 + swz_fi(r, d & 31)];
        s = mask[b * SEQ + l] ? s : -1e9f;
        float p = __expf(fminf(s, 60.f));
        lsum += p;
        const float* vb2 = v + (tb + kt) * 8192;
        for (int d = 0; d < 64; ++d) o[d] += p * vb2[(r >> 5) * 2048 + swz_fi(d, r & 31)];
    }
    float linv = 1.f / lsum;
    for (int ch = 0; ch < 2; ++ch) {
        float* dstb = ctx + ((size_t)(b * (SEQ / 128) + qt) * (D_EMBED / 32) + h * 2 + ch) * 4096;
        for (int j = 0; j < 32; ++j)
            dstb[swz_fi(rr, j)] = o[ch * 32 + j] * linv;
    }
#endif
}

// ---------------- LayerNorm (optionally emits A-swizzled copy) ------------------
__global__ __launch_bounds__(128)
void ln_k(const float* __restrict__ in, const float* __restrict__ gam,
          const float* __restrict__ bet, float* __restrict__ out,
          float* __restrict__ out_aswz)
{
    const int row = blockIdx.x;
    const int tid = threadIdx.x;
    float4 vx = ((const float4*)(in + (size_t)row * D_EMBED))[tid];
    float s  = vx.x + vx.y + vx.z + vx.w;
    float ss = vx.x * vx.x + vx.y * vx.y + vx.z * vx.z + vx.w * vx.w;
    #pragma unroll
    for (int o = 16; o; o >>= 1) {
        s  += __shfl_xor_sync(0xffffffffu, s, o);
        ss += __shfl_xor_sync(0xffffffffu, ss, o);
    }
    __shared__ float sh[8];
    if ((tid & 31) == 0) { sh[tid >> 5] = s; sh[4 + (tid >> 5)] = ss; }
    __syncthreads();
    float S  = sh[0] + sh[1] + sh[2] + sh[3];
    float SS = sh[4] + sh[5] + sh[6] + sh[7];
    float mu   = S * (1.f / 512.f);
    float var  = SS * (1.f / 512.f) - mu * mu;
    float rstd = rsqrtf(var + 1e-5f);
    float4 g  = ((const float4*)gam)[tid];
    float4 bb = ((const float4*)bet)[tid];
    float4 o;
    o.x = (vx.x - mu) * rstd * g.x + bb.x;
    o.y = (vx.y - mu) * rstd * g.y + bb.y;
    o.z = (vx.z - mu) * rstd * g.z + bb.z;
    o.w = (vx.w - mu) * rstd * g.w + bb.w;
    ((float4*)(out + (size_t)row * D_EMBED))[tid] = o;
    if (out_aswz) {
        int kk = tid * 4;
        int blk = (row >> 7) * 16 + (kk >> 5);
        *(float4*)(out_aswz + (size_t)blk * 4096 + swz_fi(row & 127, kk & 31)) = o;
    }
}

// ---------------- launcher -------------------------------------------------------
extern "C" void kernel_launch(void* const* d_in, const int* in_sizes, int n_in,
                              void* d_out, int out_size)
{
    const float* x    = (const float*)d_in[0];
    const int*   mask = (const int*)  d_in[1];
    const float* Wq   = (const float*)d_in[2];
    const float* bq   = (const float*)d_in[3];
    const float* Wk   = (const float*)d_in[4];
    const float* bk   = (const float*)d_in[5];
    const float* Wv   = (const float*)d_in[6];
    const float* bv   = (const float*)d_in[7];
    const float* Wo   = (const float*)d_in[8];
    const float* bo   = (const float*)d_in[9];

    const float *ln1g, *ln1b, *ln2g, *ln2b, *W1, *b1, *W2, *b2;
    if (in_sizes[12] == D_EMBED * DFF) {
        ln1g = (const float*)d_in[10]; ln1b = (const float*)d_in[11];
        W1   = (const float*)d_in[12]; b1   = (const float*)d_in[13];
        W2   = (const float*)d_in[14]; b2   = (const float*)d_in[15];
        ln2g = (const float*)d_in[16]; ln2b = (const float*)d_in[17];
    } else {
        ln1g = (const float*)d_in[10]; ln1b = (const float*)d_in[11];
        ln2g = (const float*)d_in[12]; ln2b = (const float*)d_in[13];
        W1   = (const float*)d_in[14]; b1   = (const float*)d_in[15];
        W2   = (const float*)d_in[16]; b2   = (const float*)d_in[17];
    }

    float *q, *k, *v, *ctx, *res1, *h, *hs, *xs, *ff, *res2;
    float *wqkvt, *wot, *w1t, *w2t;
    cudaGetSymbolAddress((void**)&q,    g_q);
    cudaGetSymbolAddress((void**)&k,    g_k);
    cudaGetSymbolAddress((void**)&v,    g_v);
    cudaGetSymbolAddress((void**)&ctx,  g_ctx);
    cudaGetSymbolAddress((void**)&res1, g_res1);
    cudaGetSymbolAddress((void**)&h,    g_h);
    cudaGetSymbolAddress((void**)&hs,   g_hs);
    cudaGetSymbolAddress((void**)&xs,   g_xs);
    cudaGetSymbolAddress((void**)&ff,   g_ff);
    cudaGetSymbolAddress((void**)&res2, g_res2);
    cudaGetSymbolAddress((void**)&wqkvt, g_wqkvt);
    cudaGetSymbolAddress((void**)&wot,   g_wot);
    cudaGetSymbolAddress((void**)&w1t,   g_w1t);
    cudaGetSymbolAddress((void**)&w2t,   g_w2t);

    static bool attr_done = false;
    if (!attr_done) {
        cudaFuncSetAttribute(attn_k, cudaFuncAttributeMaxDynamicSharedMemorySize, ATTN_SMEM);
        cudaFuncSetAttribute((gemmT<0,2>), cudaFuncAttributeMaxDynamicSharedMemorySize, GEMM_SMEM_S2);
        cudaFuncSetAttribute((gemmT<3,2>), cudaFuncAttributeMaxDynamicSharedMemorySize, GEMM_SMEM_S2);
        cudaFuncSetAttribute((gemmT<2,3>), cudaFuncAttributeMaxDynamicSharedMemorySize, GEMM_SMEM_S3);
        attr_done = true;
    }

    prep_all<<<12288, 256>>>(Wq, Wk, Wv, Wo, W1, W2, wqkvt, wot, w1t, w2t);
    swz_a<<<4096, 256>>>(x, xs);

    gemmT<0,2><<<dim3(6, 64), 256, GEMM_SMEM_S2>>>(xs, wqkvt, bq, bk, bv, nullptr,
                                                   q, k, v, 3 * D_EMBED, D_EMBED);

    attn_k<<<dim3(SEQ / 128, NHEAD, BATCH), 256, ATTN_SMEM>>>(q, k, v, mask, ctx);

    gemmT<2,3><<<dim3(2, 64), 256, GEMM_SMEM_S3>>>(ctx, wot, bo, nullptr, nullptr, x,
                                                   res1, nullptr, nullptr, D_EMBED, D_EMBED);
    ln_k<<<NROWS, 128>>>(res1, ln1g, ln1b, h, hs);

    gemmT<3,2><<<dim3(8, 64), 256, GEMM_SMEM_S2>>>(hs, w1t, b1, nullptr, nullptr, nullptr,
                                                   ff, nullptr, nullptr, DFF, D_EMBED);
    gemmT<2,3><<<dim3(2, 64), 256, GEMM_SMEM_S3>>>(ff, w2t, b2, nullptr, nullptr, h,
                                                   res2, nullptr, nullptr, D_EMBED, DFF);
    ln_k<<<NROWS, 128>>>(res2, ln2g, ln2b, (float*)d_out, nullptr);
}

// round 16
// speedup vs baseline: 1.2885x; 1.2885x over previous
#include <cuda_runtime.h>
#include <math.h>
#include <stdint.h>

#define D_EMBED 512
#define NHEAD   8
#define DH      64
#define DFF     2048
#define BATCH   2
#define SEQ     4096
#define NROWS   (BATCH*SEQ)   // 8192

#if defined(__CUDA_ARCH__)
# if defined(__CUDA_ARCH_HAS_FEATURE__)
#  if __CUDA_ARCH_HAS_FEATURE__(SM103_ALL)
#   define HAS_TC 1
#  endif
# endif
# if !defined(HAS_TC) && defined(__CUDA_ARCH_SPECIFIC__)
#  define HAS_TC 1
# endif
#endif
#ifndef HAS_TC
# define HAS_TC 0
#endif

// ---------------- scratch ------------------------------------------------------
__device__ float g_q[BATCH*NHEAD*SEQ*DH];
__device__ float g_k[BATCH*NHEAD*SEQ*DH];
__device__ float g_v[BATCH*NHEAD*SEQ*DH];
__device__ float g_ctx[NROWS*D_EMBED];
__device__ float g_ff[(size_t)NROWS*DFF];
__device__ float g_res1[NROWS*D_EMBED];
__device__ float g_h[NROWS*D_EMBED];
__device__ float g_hs[NROWS*D_EMBED];
__device__ float g_xs[NROWS*D_EMBED];
__device__ float g_res2[NROWS*D_EMBED];
__device__ float g_wqkvt[3*D_EMBED*D_EMBED];
__device__ float g_wot[D_EMBED*D_EMBED];
__device__ float g_w1t[DFF*D_EMBED];
__device__ float g_w2t[D_EMBED*DFF];

// ---------------- helpers ------------------------------------------------------
__device__ __forceinline__ float gelu_f(float x) {
    return 0.5f * x * (1.0f + erff(x * 0.70710678118654752f));
}
__device__ __forceinline__ uint32_t smem_u32(const void* p) {
    uint32_t a;
    asm("{ .reg .u64 t; cvta.to.shared.u64 t, %1; cvt.u32.u64 %0, t; }" : "=r"(a) : "l"(p));
    return a;
}
__device__ __forceinline__ int swz_fi(int r, int j) {
    int g = j >> 2;
    return r * 32 + ((g ^ (r & 7)) << 2) + (j & 3);
}
__device__ __forceinline__ float ld_swz(const float* Wt, int NC, int n, int k) {
    int blk = (n >> 8) * NC + (k >> 5);
    int off = (n & 255) * 128 + (k & 31) * 4;
    int sw = off ^ ((off >> 3) & 0x70);
    return *(const float*)((const char*)(Wt + (size_t)blk * 8192) + sw);
}

#if HAS_TC
__device__ __forceinline__ uint32_t elect_one_pred() {
    uint32_t pred;
    asm volatile("{\n\t.reg .pred p;\n\telect.sync _|p, 0xFFFFFFFF;\n\t"
                 "selp.b32 %0, 1, 0, p;\n\t}" : "=r"(pred));
    return pred;
}
#define MBAR_INIT(a, n) asm volatile("mbarrier.init.shared.b64 [%0], %1;" :: "r"(a), "r"(n) : "memory")
#define MBAR_EXPECT_TX(a, bytes) \
    asm volatile("mbarrier.arrive.expect_tx.shared.b64 _, [%0], %1;" :: "r"(a), "r"(bytes) : "memory")
#define MBAR_WAIT(a, par) do { \
    uint32_t _m = (a), _p = (par), _d; \
    asm volatile("{\n\t.reg .pred p;\n\t" \
        "mbarrier.try_wait.parity.acquire.cta.shared::cta.b64 p, [%1], %2;\n\t" \
        "selp.b32 %0, 1, 0, p;\n\t}" : "=r"(_d) : "r"(_m), "r"(_p) : "memory"); \
    if (!_d) { asm volatile("{\n\t.reg .pred P1;\n\tWL_%=:\n\t" \
        "mbarrier.try_wait.parity.acquire.cta.shared::cta.b64 P1, [%0], %1, 0x989680;\n\t" \
        "@P1 bra.uni WD_%=;\n\tbra.uni WL_%=;\n\tWD_%=:\n\t}" \
        :: "r"(_m), "r"(_p) : "memory"); } \
} while (0)
#define BULK_CP(dst, src, sz, mb) \
    asm volatile("cp.async.bulk.shared::cluster.global.mbarrier::complete_tx::bytes [%0], [%1], %2, [%3];" \
        :: "r"(dst), "l"(src), "r"(sz), "r"(mb) : "memory")

#define TC_ALLOC(sa, n)   asm volatile("tcgen05.alloc.cta_group::1.sync.aligned.shared::cta.b32 [%0], %1;" :: "r"(sa), "r"(n) : "memory")
#define TC_RELINQ()       asm volatile("tcgen05.relinquish_alloc_permit.cta_group::1.sync.aligned;")
#define TC_DEALLOC(t, n)  asm volatile("tcgen05.dealloc.cta_group::1.sync.aligned.b32 %0, %1;" :: "r"(t), "r"(n))
#define TC_COMMIT(mb)     asm volatile("tcgen05.commit.cta_group::1.mbarrier::arrive::one.shared::cluster.b64 [%0];" :: "r"(mb) : "memory")
#define TC_FENCE_AFTER()  asm volatile("tcgen05.fence::after_thread_sync;" ::: "memory")
#define TC_FENCE_BEFORE() asm volatile("tcgen05.fence::before_thread_sync;" ::: "memory")
#define TC_WAIT_LD()      asm volatile("tcgen05.wait::ld.sync.aligned;" ::: "memory")
#define TC_WAIT_ST()      asm volatile("tcgen05.wait::st.sync.aligned;" ::: "memory")
#define FENCE_ASYNC()     asm volatile("fence.proxy.async.shared::cta;" ::: "memory")

#define TC_LD_X32(r, ta) \
    asm volatile("tcgen05.ld.sync.aligned.32x32b.x32.b32 " \
        "{%0, %1, %2, %3, %4, %5, %6, %7, %8, %9, %10, %11, %12, %13, %14, %15, " \
        " %16, %17, %18, %19, %20, %21, %22, %23, %24, %25, %26, %27, %28, %29, %30, %31}, [%32];" \
        : "=r"((r)[0]), "=r"((r)[1]), "=r"((r)[2]), "=r"((r)[3]), \
          "=r"((r)[4]), "=r"((r)[5]), "=r"((r)[6]), "=r"((r)[7]), \
          "=r"((r)[8]), "=r"((r)[9]), "=r"((r)[10]), "=r"((r)[11]), \
          "=r"((r)[12]), "=r"((r)[13]), "=r"((r)[14]), "=r"((r)[15]), \
          "=r"((r)[16]), "=r"((r)[17]), "=r"((r)[18]), "=r"((r)[19]), \
          "=r"((r)[20]), "=r"((r)[21]), "=r"((r)[22]), "=r"((r)[23]), \
          "=r"((r)[24]), "=r"((r)[25]), "=r"((r)[26]), "=r"((r)[27]), \
          "=r"((r)[28]), "=r"((r)[29]), "=r"((r)[30]), "=r"((r)[31]) \
        : "r"(ta))

#define TC_ST_X32(ta, r) \
    asm volatile("tcgen05.st.sync.aligned.32x32b.x32.b32 [%0], " \
        "{%1, %2, %3, %4, %5, %6, %7, %8, %9, %10, %11, %12, %13, %14, %15, %16, " \
        " %17, %18, %19, %20, %21, %22, %23, %24, %25, %26, %27, %28, %29, %30, %31, %32};" \
        :: "r"(ta), \
           "r"((r)[0]), "r"((r)[1]), "r"((r)[2]), "r"((r)[3]), \
           "r"((r)[4]), "r"((r)[5]), "r"((r)[6]), "r"((r)[7]), \
           "r"((r)[8]), "r"((r)[9]), "r"((r)[10]), "r"((r)[11]), \
           "r"((r)[12]), "r"((r)[13]), "r"((r)[14]), "r"((r)[15]), \
           "r"((r)[16]), "r"((r)[17]), "r"((r)[18]), "r"((r)[19]), \
           "r"((r)[20]), "r"((r)[21]), "r"((r)[22]), "r"((r)[23]), \
           "r"((r)[24]), "r"((r)[25]), "r"((r)[26]), "r"((r)[27]), \
           "r"((r)[28]), "r"((r)[29]), "r"((r)[30]), "r"((r)[31]) \
        : "memory")

#define TC_MMA_TF32(dt, ad, bd, id, en) do { \
    uint32_t _e = (en) ? 1u : 0u; \
    asm volatile("{\n\t.reg .pred p;\n\tsetp.ne.u32 p, %5, 0;\n\t" \
        "tcgen05.mma.cta_group::1.kind::tf32 [%0], %1, %2, %3, {%4, %4, %4, %4}, p;\n\t}" \
        :: "r"(dt), "l"(ad), "l"(bd), "r"(id), "r"(0u), "r"(_e) : "memory"); \
} while (0)

#define TC_MMA_TF32_TS(dt, at, bd, id, en) do { \
    uint32_t _e = (en) ? 1u : 0u; \
    asm volatile("{\n\t.reg .pred p;\n\tsetp.ne.u32 p, %5, 0;\n\t" \
        "tcgen05.mma.cta_group::1.kind::tf32 [%0], [%1], %2, %3, {%4, %4, %4, %4}, p;\n\t}" \
        :: "r"(dt), "r"(at), "l"(bd), "r"(id), "r"(0u), "r"(_e) : "memory"); \
} while (0)

__device__ __forceinline__ uint64_t make_desc(uint32_t addr) {
    return ((uint64_t)2 << 61) | ((uint64_t)1 << 46) | ((uint64_t)64 << 32) |
           ((uint64_t)1 << 16) | (uint64_t)((addr >> 4) & 0x3FFF);
}
#define IDESC_G   ((1u << 4) | (2u << 7) | (2u << 10) | (32u << 17) | (8u << 24))  // M128 N256
#define IDESC_128 ((1u << 4) | (2u << 7) | (2u << 10) | (16u << 17) | (8u << 24))  // M128 N128
#define IDESC_PV  ((1u << 4) | (2u << 7) | (2u << 10) | (8u  << 17) | (8u << 24))  // M128 N64
#endif // HAS_TC

// ---------------- weight pre-swizzle -------------------------------------------
__global__ __launch_bounds__(256)
void prep_all(const float* __restrict__ Wq, const float* __restrict__ Wk,
              const float* __restrict__ Wv, const float* __restrict__ Wo,
              const float* __restrict__ W1, const float* __restrict__ W2,
              float* __restrict__ wqkvt, float* __restrict__ wot,
              float* __restrict__ w1t, float* __restrict__ w2t)
{
    int id = blockIdx.x;
    const float* src; float* dst; int Kd, Nd, lb;
    if      (id < 1024) { src = Wq; dst = wqkvt;            Kd = 512;  Nd = 512;  lb = id; }
    else if (id < 2048) { src = Wk; dst = wqkvt + 512*512;  Kd = 512;  Nd = 512;  lb = id - 1024; }
    else if (id < 3072) { src = Wv; dst = wqkvt + 2*512*512;Kd = 512;  Nd = 512;  lb = id - 2048; }
    else if (id < 4096) { src = Wo; dst = wot;              Kd = 512;  Nd = 512;  lb = id - 3072; }
    else if (id < 8192) { src = W1; dst = w1t;              Kd = 512;  Nd = 2048; lb = id - 4096; }
    else                { src = W2; dst = w2t;              Kd = 2048; Nd = 512;  lb = id - 8192; }
    int e = lb * 256 + threadIdx.x;
    int k = e / Nd, n = e % Nd;
    float v = src[e];
    int NC = Kd >> 5;
    int blk = (n >> 8) * NC + (k >> 5);
    int off = (n & 255) * 128 + (k & 31) * 4;
    int sw = off ^ ((off >> 3) & 0x70);
    *(float*)((char*)(dst + (size_t)blk * 8192) + sw) = v;
}

// ---------------- x row-major -> A-swizzled ------------------------------------
__global__ __launch_bounds__(256)
void swz_a(const float* __restrict__ src, float* __restrict__ dst)
{
    int idx = blockIdx.x * 256 + threadIdx.x;
    int e = idx * 4;
    int m = e >> 9, k = e & 511;
    float4 v = *(const float4*)(src + (size_t)e);
    int blk = (m >> 7) * 16 + (k >> 5);
    *(float4*)(dst + (size_t)blk * 4096 + swz_fi(m & 127, k & 31)) = v;
}

// ---------------- GEMM ----------------------------------------------------------
#define GEMM_SMEM_S2  98304
#define GEMM_SMEM_S3  147456
template<int MODE, int STAGES>
__global__ __launch_bounds__(256, 2)
void gemmT(const float* __restrict__ A, const float* __restrict__ Wt,
           const float* __restrict__ bias0, const float* __restrict__ bias1,
           const float* __restrict__ bias2, const float* __restrict__ resid,
           float* __restrict__ out0, float* __restrict__ out1, float* __restrict__ out2,
           int N, int K)
{
    extern __shared__ __align__(1024) float sm[];
    const int tid = threadIdx.x, wid = tid >> 5, lane = tid & 31;
    const int n0 = blockIdx.x * 256, m0 = blockIdx.y * 128;
    const int NC = K >> 5;

#if HAS_TC
    __shared__ uint32_t s_tptr;
    __shared__ unsigned long long s_mb[6];
    const uint32_t smb = smem_u32(sm);
    const uint32_t BOF = STAGES * 16384u;

    if (wid == 0) { TC_ALLOC(smem_u32(&s_tptr), 256); TC_RELINQ(); }
    if (tid == 0) {
        #pragma unroll
        for (int i = 0; i < 6; ++i) MBAR_INIT(smem_u32(&s_mb[i]), 1);
    }
    __syncthreads();
    const uint32_t tmem = s_tptr;
    uint32_t mbB[3] = {smem_u32(&s_mb[0]), smem_u32(&s_mb[1]), smem_u32(&s_mb[2])};
    uint32_t mbM[3] = {smem_u32(&s_mb[3]), smem_u32(&s_mb[4]), smem_u32(&s_mb[5])};

    if (tid == 0) {
        int cB[3] = {0, 0, 0}, cM[3] = {0, 0, 0};
        const size_t ablk = (size_t)blockIdx.y * NC;
        const size_t bblk = (size_t)blockIdx.x * NC;
        #pragma unroll
        for (int s = 0; s < STAGES; ++s) {
            MBAR_EXPECT_TX(mbB[s], 49152u);
            BULK_CP(smb + s * 16384, (const void*)(A + (ablk + s) * 4096), 16384u, mbB[s]);
            BULK_CP(smb + BOF + s * 32768, (const void*)(Wt + (bblk + s) * 8192), 32768u, mbB[s]);
        }
        for (int s = 0; s < NC; ++s) {
            const int buf = s % STAGES;
            MBAR_WAIT(mbB[buf], cB[buf] & 1); cB[buf]++;
            uint64_t ad = make_desc(smb + buf * 16384);
            uint64_t bd = make_desc(smb + BOF + buf * 32768);
            #pragma unroll
            for (int s2 = 0; s2 < 4; ++s2)
                TC_MMA_TF32(tmem, ad + 2 * s2, bd + 2 * s2, IDESC_G, (s > 0) || (s2 > 0));
            TC_COMMIT(mbM[buf]);
            if (s + STAGES < NC) {
                MBAR_WAIT(mbM[buf], cM[buf] & 1); cM[buf]++;
                MBAR_EXPECT_TX(mbB[buf], 49152u);
                BULK_CP(smb + buf * 16384, (const void*)(A + (ablk + s + STAGES) * 4096),
                        16384u, mbB[buf]);
                BULK_CP(smb + BOF + buf * 32768, (const void*)(Wt + (bblk + s + STAGES) * 8192),
                        32768u, mbB[buf]);
            }
        }
        #pragma unroll
        for (int b2 = 0; b2 < STAGES; ++b2) {
            int cnt = (NC - b2 + STAGES - 1) / STAGES;
            if (cnt > cM[b2]) MBAR_WAIT(mbM[b2], (cnt - 1) & 1);
        }
    }
    __syncthreads();
    TC_FENCE_AFTER();

    const int sp = wid & 3, chh = wid >> 2;
    for (int cg = 0; cg < 4; ++cg) {
        uint32_t r[32];
        TC_LD_X32(r, tmem + cg * 64 + chh * 32);
        TC_WAIT_LD();
        const int row = sp * 32 + lane;
        #pragma unroll
        for (int j = 0; j < 32; ++j) sm[row * 65 + chh * 32 + j] = __uint_as_float(r[j]);
        __syncthreads();

        const int nb = n0 + cg * 64;
        if (MODE == 0) {
            const int which = nb >> 9;
            const int hh = (nb >> 6) & 7;
            const int b_ = m0 >> 12;
            const int tile = (m0 & 4095) >> 7;
            const size_t tbase = ((size_t)(b_ * NHEAD + hh) * (SEQ / 128) + tile) * 8192;
            if (which < 2) {
                const int r2 = tid & 127, sel = tid >> 7;
                const float* bp = which ? bias1 : bias0;
                float* outw = which ? out1 : out0;
                const float scale = which ? 1.f : 0.125f;
                const float* src = &sm[r2 * 65 + sel * 32];
                float vv[32];
                #pragma unroll
                for (int j = 0; j < 32; ++j)
                    vv[j] = (src[j] + bp[(nb & 511) + sel * 32 + j]) * scale;
                float* dstb = outw + tbase + sel * 4096 + r2 * 32;
                #pragma unroll
                for (int g = 0; g < 8; ++g)
                    *(float4*)(dstb + ((g ^ (r2 & 7)) << 2)) =
                        make_float4(vv[g * 4], vv[g * 4 + 1], vv[g * 4 + 2], vv[g * 4 + 3]);
            } else {
                const int dloc = tid & 63, kg = tid >> 6;
                const float bia = bias2[(nb & 511) + dloc];
                float vv[32];
                #pragma unroll
                for (int i = 0; i < 32; ++i)
                    vv[i] = sm[(kg * 32 + i) * 65 + dloc] + bia;
                float* dstb = out2 + tbase + kg * 2048 + dloc * 32;
                #pragma unroll
                for (int g = 0; g < 8; ++g)
                    *(float4*)(dstb + ((g ^ (dloc & 7)) << 2)) =
                        make_float4(vv[g * 4], vv[g * 4 + 1], vv[g * 4 + 2], vv[g * 4 + 3]);
            }
        } else if (MODE == 2) {
            const int r2 = tid & 127, sel = tid >> 7;
            const int m = m0 + r2;
            const int n = nb + sel * 32;
            const float* src = &sm[r2 * 65 + sel * 32];
            float* dst = out0 + (size_t)m * N + n;
            const float* rs = resid + (size_t)m * N + n;
            #pragma unroll
            for (int g = 0; g < 8; ++g) {
                float4 b4 = *(const float4*)(bias0 + n + g * 4);
                float4 r4 = *(const float4*)(rs + g * 4);
                *(float4*)(dst + g * 4) = make_float4(
                    src[g * 4 + 0] + b4.x + r4.x, src[g * 4 + 1] + b4.y + r4.y,
                    src[g * 4 + 2] + b4.z + r4.z, src[g * 4 + 3] + b4.w + r4.w);
            }
        } else {
            const int r2 = tid & 127, sel = tid >> 7;
            const int n = nb + sel * 32;
            const float* src = &sm[r2 * 65 + sel * 32];
            float vv[32];
            #pragma unroll
            for (int j = 0; j < 32; ++j) vv[j] = gelu_f(src[j] + bias0[n + j]);
            float* dstb = out0 + ((size_t)(m0 >> 7) * (DFF / 32) + (n >> 5)) * 4096 + r2 * 32;
            #pragma unroll
            for (int g = 0; g < 8; ++g)
                *(float4*)(dstb + ((g ^ (r2 & 7)) << 2)) =
                    make_float4(vv[g * 4], vv[g * 4 + 1], vv[g * 4 + 2], vv[g * 4 + 3]);
        }
        __syncthreads();
    }
    if (wid == 0) TC_DEALLOC(tmem, 256);

#else
    for (int e = tid; e < 128 * 256; e += 256) {
        int mr = e & 127, nc = e >> 7;
        int m = m0 + mr, n = n0 + nc;
        float acc = 0.f;
        for (int k = 0; k < K; ++k) {
            float a = A[((size_t)(m >> 7) * NC + (k >> 5)) * 4096 + swz_fi(m & 127, k & 31)];
            acc += a * ld_swz(Wt, NC, n, k);
        }
        if (MODE == 0) {
            int which = n >> 9, hh = (n >> 6) & 7;
            int b_ = m >> 12, l = m & (SEQ - 1);
            size_t tbase = ((size_t)(b_ * NHEAD + hh) * (SEQ / 128) + (l >> 7)) * 8192;
            if (which < 2) {
                const float* bp = which ? bias1 : bias0;
                float* outw = which ? out1 : out0;
                float val = (acc + bp[n & 511]) * (which ? 1.f : 0.125f);
                outw[tbase + ((n >> 5) & 1) * 4096 + swz_fi(l & 127, n & 31)] = val;
            } else {
                out2[tbase + ((l & 127) >> 5) * 2048 + swz_fi(n & 63, l & 31)] = acc + bias2[n & 511];
            }
        } else if (MODE == 2) {
            out0[(size_t)m * N + n] = acc + bias0[n] + resid[(size_t)m * N + n];
        } else {
            out0[((size_t)(m >> 7) * (DFF / 32) + (n >> 5)) * 4096 + swz_fi(m & 127, n & 31)] =
                gelu_f(acc + bias0[n]);
        }
    }
#endif
}

// ---------------- attention: BQ=128, Q in TMEM, 2 CTAs/SM -----------------------
#define ATTN_SMEM 101376

__global__ __launch_bounds__(256, 2)
void attn_k(const float* __restrict__ q, const float* __restrict__ k,
            const float* __restrict__ v, const int* __restrict__ mask,
            float* __restrict__ ctx)
{
    extern __shared__ __align__(1024) float sm[];
    const int qt = blockIdx.x, h = blockIdx.y, b = blockIdx.z;
    const int tid = threadIdx.x;
    const size_t tb = (size_t)(b * NHEAD + h) * (SEQ / 128);

#if HAS_TC
    float* Ks  = sm;                  // 2 x 8192 (slot0 stages Q first)
    float* Vs  = sm + 16384;          // 8192
    float* lpart = sm + 24576;        // 256
    int*   Msm = (int*)(sm + 24832);  // [4][128]

    __shared__ uint32_t s_tptr;
    __shared__ unsigned long long s_mb[6];   // Q K0 K1 V S O
    const int wid = tid >> 5, lane = tid & 31;
    const int sp = wid & 3, chh = wid >> 2;
    const int NT = SEQ / 128;

    if (wid == 0) { TC_ALLOC(smem_u32(&s_tptr), 256); TC_RELINQ(); }
    if (tid == 0) {
        #pragma unroll
        for (int i = 0; i < 6; ++i) MBAR_INIT(smem_u32(&s_mb[i]), 1);
    }
    __syncthreads();
    const uint32_t tmem = s_tptr;
    const uint32_t mbQ = smem_u32(&s_mb[0]);
    uint32_t mbK[2] = {smem_u32(&s_mb[1]), smem_u32(&s_mb[2])};
    const uint32_t mbV = smem_u32(&s_mb[3]);
    const uint32_t mbS = smem_u32(&s_mb[4]);
    const uint32_t mbO = smem_u32(&s_mb[5]);
    const uint32_t S_T = tmem, O_T = tmem + 128, Q_T = tmem + 192;

    #define ISSUE_QK(kbuf) do { \
        uint64_t kd = make_desc(smem_u32(Ks + (kbuf) * 8192)); \
        _Pragma("unroll") \
        for (int c = 0; c < 2; ++c) \
            _Pragma("unroll") \
            for (int s = 0; s < 4; ++s) \
                TC_MMA_TF32_TS(S_T, Q_T + (c * 4 + s) * 8, kd + c * 1024 + 2 * s, \
                               IDESC_128, (c > 0) || (s > 0)); \
        TC_COMMIT(mbS); \
    } while (0)

    #define ISSUE_PV(t) do { \
        _Pragma("unroll") \
        for (int cc = 0; cc < 4; ++cc) { \
            uint64_t vd = make_desc(smem_u32(Vs + cc * 2048)); \
            _Pragma("unroll") \
            for (int s = 0; s < 4; ++s) \
                TC_MMA_TF32_TS(O_T, S_T + cc * 32 + s * 8, vd + 2 * s, IDESC_PV, \
                               ((t) > 0) || (cc > 0) || (s > 0)); \
        } \
        TC_COMMIT(mbO); \
    } while (0)

    #define SOFTMAX(tslot, lsum) do { \
        uint32_t ra[32], rb[32]; \
        TC_LD_X32(ra, S_T + chh * 64); \
        TC_WAIT_LD(); \
        TC_LD_X32(rb, S_T + chh * 64 + 32); \
        const int* mrow = &Msm[(tslot) * 128 + chh * 64]; \
        _Pragma("unroll") \
        for (int j = 0; j < 32; ++j) { \
            float s = __uint_as_float(ra[j]); \
            s = mrow[j] ? s : -1e9f; \
            float p = __expf(fminf(s, 60.f)); \
            (lsum) += p; \
            ra[j] = __float_as_uint(p); \
        } \
        TC_WAIT_LD(); \
        TC_ST_X32(S_T + chh * 64, ra); \
        _Pragma("unroll") \
        for (int j = 0; j < 32; ++j) { \
            float s = __uint_as_float(rb[j]); \
            s = mrow[32 + j] ? s : -1e9f; \
            float p = __expf(fminf(s, 60.f)); \
            (lsum) += p; \
            rb[j] = __float_as_uint(p); \
        } \
        TC_ST_X32(S_T + chh * 64 + 32, rb); \
        TC_WAIT_ST(); \
        TC_FENCE_BEFORE(); \
    } while (0)

    // ---- prologue: Q -> K-slot0, K(0) -> slot1, V(0) ----
    // K(j) slot: 1 - (j & 1)  (K0->1, K1->0, K2->1, ...)
    if (tid == 0) {
        MBAR_EXPECT_TX(mbQ, 32768u);
        BULK_CP(smem_u32(Ks), (const void*)(q + (tb + qt) * 8192), 32768u, mbQ);
        MBAR_EXPECT_TX(mbK[1], 32768u);
        BULK_CP(smem_u32(Ks + 8192), (const void*)(k + tb * 8192), 32768u, mbK[1]);
        MBAR_EXPECT_TX(mbV, 32768u);
        BULK_CP(smem_u32(Vs), (const void*)(v + tb * 8192), 32768u, mbV);
    }
    if (tid < 128) {
        Msm[tid] = mask[b * SEQ + tid];
        Msm[128 + tid] = mask[b * SEQ + 128 + tid];
    }
    MBAR_WAIT(mbQ, 0);
    if (wid < 4) {
        const int row = wid * 32 + lane;
        #pragma unroll
        for (int cchunk = 0; cchunk < 2; ++cchunk) {
            uint32_t qr[32];
            const float* base = Ks + cchunk * 4096 + row * 32;
            #pragma unroll
            for (int g = 0; g < 8; ++g) {
                float4 f = *(const float4*)(base + ((g ^ (row & 7)) << 2));
                qr[g * 4 + 0] = __float_as_uint(f.x);
                qr[g * 4 + 1] = __float_as_uint(f.y);
                qr[g * 4 + 2] = __float_as_uint(f.z);
                qr[g * 4 + 3] = __float_as_uint(f.w);
            }
            TC_ST_X32(Q_T + cchunk * 32, qr);
        }
        TC_WAIT_ST();
    }
    TC_FENCE_BEFORE();
    __syncthreads();

    int cK[2] = {0, 0}, cV = 0;
    if (tid == 0) {
        TC_FENCE_AFTER();
        MBAR_WAIT(mbK[1], 0); cK[1] = 1;
        ISSUE_QK(1);
        if (1 < NT) {
            MBAR_EXPECT_TX(mbK[0], 32768u);
            BULK_CP(smem_u32(Ks), (const void*)(k + (tb + 1) * 8192), 32768u, mbK[0]);
        }
    }

    float lsum = 0.f;

    for (int t = 0; t < NT; ++t) {
        MBAR_WAIT(mbS, t & 1);
        TC_FENCE_AFTER();
        SOFTMAX((t & 3), lsum);
        __syncthreads();
        if (tid == 0) {
            TC_FENCE_AFTER();
            MBAR_WAIT(mbV, cV & 1); cV++;
            ISSUE_PV(t);
            MBAR_WAIT(mbO, t & 1);
            if (t + 1 < NT) {
                MBAR_EXPECT_TX(mbV, 32768u);
                BULK_CP(smem_u32(Vs), (const void*)(v + (tb + t + 1) * 8192), 32768u, mbV);
                const int kb = t & 1;            // slot of K(t+1)
                MBAR_WAIT(mbK[kb], cK[kb] & 1); cK[kb]++;
                ISSUE_QK(kb);
                if (t + 2 < NT) {
                    const int kb2 = 1 - kb;      // slot of K(t+2)
                    MBAR_EXPECT_TX(mbK[kb2], 32768u);
                    BULK_CP(smem_u32(Ks + kb2 * 8192), (const void*)(k + (tb + t + 2) * 8192),
                            32768u, mbK[kb2]);
                }
            }
        }
        if (t + 2 < NT && tid < 128)
            Msm[((t + 2) & 3) * 128 + tid] = mask[b * SEQ + (t + 2) * 128 + tid];
        __syncthreads();
    }

    // ---- combine l, read O, normalize, store ctx (A-swizzled layout) ----
    const int rr = sp * 32 + lane;
    lpart[chh * 128 + rr] = lsum;
    __syncthreads();
    float linv = 1.f / (lpart[rr] + lpart[128 + rr]);

    TC_FENCE_AFTER();
    uint32_t ro[32];
    TC_LD_X32(ro, O_T + chh * 32);
    TC_WAIT_LD();
    float vv[32];
    #pragma unroll
    for (int j = 0; j < 32; ++j) vv[j] = __uint_as_float(ro[j]) * linv;
    float* dstb = ctx + ((size_t)(b * (SEQ / 128) + qt) * (D_EMBED / 32) + h * 2 + chh) * 4096
                      + rr * 32;
    #pragma unroll
    for (int g = 0; g < 8; ++g)
        *(float4*)(dstb + ((g ^ (rr & 7)) << 2)) =
            make_float4(vv[g * 4], vv[g * 4 + 1], vv[g * 4 + 2], vv[g * 4 + 3]);
    __syncthreads();
    if (wid == 0) TC_DEALLOC(tmem, 256);
    #undef ISSUE_QK
    #undef ISSUE_PV
    #undef SOFTMAX

#else
    // naive correct fallback (never runs on sm_103a HW)
    if (tid >= 128) return;
    const int rr = tid;
    const float* qb2 = q + (tb + qt) * 8192;
    float qv[64], o[64];
    #pragma unroll
    for (int d = 0; d < 64; ++d) {
        qv[d] = qb2[(d >> 5) * 4096 + swz_fi(rr, d & 31)];
        o[d] = 0.f;
    }
    float lsum = 0.f;
    for (int l = 0; l < SEQ; ++l) {
        int kt = l >> 7, r = l & 127;
        const float* kb2 = k + (tb + kt) * 8192;
        float s = 0.f;
        for (int d = 0; d < 64; ++d) s += qv[d] * kb2[(d >> 5) * 4096 + swz_fi(r, d & 31)];
        s = mask[b * SEQ + l] ? s : -1e9f;
        float p = __expf(fminf(s, 60.f));
        lsum += p;
        const float* vb2 = v + (tb + kt) * 8192;
        for (int d = 0; d < 64; ++d) o[d] += p * vb2[(r >> 5) * 2048 + swz_fi(d, r & 31)];
    }
    float linv = 1.f / lsum;
    for (int ch = 0; ch < 2; ++ch) {
        float* dstb = ctx + ((size_t)(b * (SEQ / 128) + qt) * (D_EMBED / 32) + h * 2 + ch) * 4096;
        for (int j = 0; j < 32; ++j)
            dstb[swz_fi(rr, j)] = o[ch * 32 + j] * linv;
    }
#endif
}

// ---------------- LayerNorm (optionally emits A-swizzled copy) ------------------
__global__ __launch_bounds__(128)
void ln_k(const float* __restrict__ in, const float* __restrict__ gam,
          const float* __restrict__ bet, float* __restrict__ out,
          float* __restrict__ out_aswz)
{
    const int row = blockIdx.x;
    const int tid = threadIdx.x;
    float4 vx = ((const float4*)(in + (size_t)row * D_EMBED))[tid];
    float s  = vx.x + vx.y + vx.z + vx.w;
    float ss = vx.x * vx.x + vx.y * vx.y + vx.z * vx.z + vx.w * vx.w;
    #pragma unroll
    for (int o = 16; o; o >>= 1) {
        s  += __shfl_xor_sync(0xffffffffu, s, o);
        ss += __shfl_xor_sync(0xffffffffu, ss, o);
    }
    __shared__ float sh[8];
    if ((tid & 31) == 0) { sh[tid >> 5] = s; sh[4 + (tid >> 5)] = ss; }
    __syncthreads();
    float S  = sh[0] + sh[1] + sh[2] + sh[3];
    float SS = sh[4] + sh[5] + sh[6] + sh[7];
    float mu   = S * (1.f / 512.f);
    float var  = SS * (1.f / 512.f) - mu * mu;
    float rstd = rsqrtf(var + 1e-5f);
    float4 g  = ((const float4*)gam)[tid];
    float4 bb = ((const float4*)bet)[tid];
    float4 o;
    o.x = (vx.x - mu) * rstd * g.x + bb.x;
    o.y = (vx.y - mu) * rstd * g.y + bb.y;
    o.z = (vx.z - mu) * rstd * g.z + bb.z;
    o.w = (vx.w - mu) * rstd * g.w + bb.w;
    ((float4*)(out + (size_t)row * D_EMBED))[tid] = o;
    if (out_aswz) {
        int kk = tid * 4;
        int blk = (row >> 7) * 16 + (kk >> 5);
        *(float4*)(out_aswz + (size_t)blk * 4096 + swz_fi(row & 127, kk & 31)) = o;
    }
}

// ---------------- launcher -------------------------------------------------------
extern "C" void kernel_launch(void* const* d_in, const int* in_sizes, int n_in,
                              void* d_out, int out_size)
{
    const float* x    = (const float*)d_in[0];
    const int*   mask = (const int*)  d_in[1];
    const float* Wq   = (const float*)d_in[2];
    const float* bq   = (const float*)d_in[3];
    const float* Wk   = (const float*)d_in[4];
    const float* bk   = (const float*)d_in[5];
    const float* Wv   = (const float*)d_in[6];
    const float* bv   = (const float*)d_in[7];
    const float* Wo   = (const float*)d_in[8];
    const float* bo   = (const float*)d_in[9];

    const float *ln1g, *ln1b, *ln2g, *ln2b, *W1, *b1, *W2, *b2;
    if (in_sizes[12] == D_EMBED * DFF) {
        ln1g = (const float*)d_in[10]; ln1b = (const float*)d_in[11];
        W1   = (const float*)d_in[12]; b1   = (const float*)d_in[13];
        W2   = (const float*)d_in[14]; b2   = (const float*)d_in[15];
        ln2g = (const float*)d_in[16]; ln2b = (const float*)d_in[17];
    } else {
        ln1g = (const float*)d_in[10]; ln1b = (const float*)d_in[11];
        ln2g = (const float*)d_in[12]; ln2b = (const float*)d_in[13];
        W1   = (const float*)d_in[14]; b1   = (const float*)d_in[15];
        W2   = (const float*)d_in[16]; b2   = (const float*)d_in[17];
    }

    float *q, *k, *v, *ctx, *res1, *h, *hs, *xs, *ff, *res2;
    float *wqkvt, *wot, *w1t, *w2t;
    cudaGetSymbolAddress((void**)&q,    g_q);
    cudaGetSymbolAddress((void**)&k,    g_k);
    cudaGetSymbolAddress((void**)&v,    g_v);
    cudaGetSymbolAddress((void**)&ctx,  g_ctx);
    cudaGetSymbolAddress((void**)&res1, g_res1);
    cudaGetSymbolAddress((void**)&h,    g_h);
    cudaGetSymbolAddress((void**)&hs,   g_hs);
    cudaGetSymbolAddress((void**)&xs,   g_xs);
    cudaGetSymbolAddress((void**)&ff,   g_ff);
    cudaGetSymbolAddress((void**)&res2, g_res2);
    cudaGetSymbolAddress((void**)&wqkvt, g_wqkvt);
    cudaGetSymbolAddress((void**)&wot,   g_wot);
    cudaGetSymbolAddress((void**)&w1t,   g_w1t);
    cudaGetSymbolAddress((void**)&w2t,   g_w2t);

    static bool attr_done = false;
    if (!attr_done) {
        cudaFuncSetAttribute(attn_k, cudaFuncAttributeMaxDynamicSharedMemorySize, ATTN_SMEM);
        cudaFuncSetAttribute((gemmT<0,2>), cudaFuncAttributeMaxDynamicSharedMemorySize, GEMM_SMEM_S2);
        cudaFuncSetAttribute((gemmT<3,2>), cudaFuncAttributeMaxDynamicSharedMemorySize, GEMM_SMEM_S2);
        cudaFuncSetAttribute((gemmT<2,3>), cudaFuncAttributeMaxDynamicSharedMemorySize, GEMM_SMEM_S3);
        attr_done = true;
    }

    prep_all<<<12288, 256>>>(Wq, Wk, Wv, Wo, W1, W2, wqkvt, wot, w1t, w2t);
    swz_a<<<4096, 256>>>(x, xs);

    gemmT<0,2><<<dim3(6, 64), 256, GEMM_SMEM_S2>>>(xs, wqkvt, bq, bk, bv, nullptr,
                                                   q, k, v, 3 * D_EMBED, D_EMBED);

    attn_k<<<dim3(SEQ / 128, NHEAD, BATCH), 256, ATTN_SMEM>>>(q, k, v, mask, ctx);

    gemmT<2,3><<<dim3(2, 64), 256, GEMM_SMEM_S3>>>(ctx, wot, bo, nullptr, nullptr, x,
                                                   res1, nullptr, nullptr, D_EMBED, D_EMBED);
    ln_k<<<NROWS, 128>>>(res1, ln1g, ln1b, h, hs);

    gemmT<3,2><<<dim3(8, 64), 256, GEMM_SMEM_S2>>>(hs, w1t, b1, nullptr, nullptr, nullptr,
                                                   ff, nullptr, nullptr, DFF, D_EMBED);
    gemmT<2,3><<<dim3(2, 64), 256, GEMM_SMEM_S3>>>(ff, w2t, b2, nullptr, nullptr, h,
                                                   res2, nullptr, nullptr, D_EMBED, DFF);
    ln_k<<<NROWS, 128>>>(res2, ln2g, ln2b, (float*)d_out, nullptr);
}

// round 17
// speedup vs baseline: 1.3336x; 1.0350x over previous
#include <cuda_runtime.h>
#include <math.h>
#include <stdint.h>

#define D_EMBED 512
#define NHEAD   8
#define DH      64
#define DFF     2048
#define BATCH   2
#define SEQ     4096
#define NROWS   (BATCH*SEQ)   // 8192

#if defined(__CUDA_ARCH__)
# if defined(__CUDA_ARCH_HAS_FEATURE__)
#  if __CUDA_ARCH_HAS_FEATURE__(SM103_ALL)
#   define HAS_TC 1
#  endif
# endif
# if !defined(HAS_TC) && defined(__CUDA_ARCH_SPECIFIC__)
#  define HAS_TC 1
# endif
#endif
#ifndef HAS_TC
# define HAS_TC 0
#endif

// ---------------- scratch ------------------------------------------------------
__device__ float g_q[BATCH*NHEAD*SEQ*DH];
__device__ float g_k[BATCH*NHEAD*SEQ*DH];
__device__ float g_v[BATCH*NHEAD*SEQ*DH];
__device__ float g_ctx[NROWS*D_EMBED];
__device__ float g_ff[(size_t)NROWS*DFF];
__device__ float g_res1[NROWS*D_EMBED];
__device__ float g_h[NROWS*D_EMBED];
__device__ float g_hs[NROWS*D_EMBED];
__device__ float g_xs[NROWS*D_EMBED];
__device__ float g_res2[NROWS*D_EMBED];
__device__ float g_wqkvt[3*D_EMBED*D_EMBED];
__device__ float g_wot[D_EMBED*D_EMBED];
__device__ float g_w1t[DFF*D_EMBED];
__device__ float g_w2t[D_EMBED*DFF];

// ---------------- helpers ------------------------------------------------------
__device__ __forceinline__ float gelu_f(float x) {
    return 0.5f * x * (1.0f + erff(x * 0.70710678118654752f));
}
__device__ __forceinline__ uint32_t smem_u32(const void* p) {
    uint32_t a;
    asm("{ .reg .u64 t; cvta.to.shared.u64 t, %1; cvt.u32.u64 %0, t; }" : "=r"(a) : "l"(p));
    return a;
}
__device__ __forceinline__ int swz_fi(int r, int j) {
    int g = j >> 2;
    return r * 32 + ((g ^ (r & 7)) << 2) + (j & 3);
}
__device__ __forceinline__ float ld_swz(const float* Wt, int NC, int n, int k) {
    int blk = (n >> 8) * NC + (k >> 5);
    int off = (n & 255) * 128 + (k & 31) * 4;
    int sw = off ^ ((off >> 3) & 0x70);
    return *(const float*)((const char*)(Wt + (size_t)blk * 8192) + sw);
}

#if HAS_TC
__device__ __forceinline__ uint32_t elect_one_pred() {
    uint32_t pred;
    asm volatile("{\n\t.reg .pred p;\n\telect.sync _|p, 0xFFFFFFFF;\n\t"
                 "selp.b32 %0, 1, 0, p;\n\t}" : "=r"(pred));
    return pred;
}
#define MBAR_INIT(a, n) asm volatile("mbarrier.init.shared.b64 [%0], %1;" :: "r"(a), "r"(n) : "memory")
#define MBAR_EXPECT_TX(a, bytes) \
    asm volatile("mbarrier.arrive.expect_tx.shared.b64 _, [%0], %1;" :: "r"(a), "r"(bytes) : "memory")
#define MBAR_WAIT(a, par) do { \
    uint32_t _m = (a), _p = (par), _d; \
    asm volatile("{\n\t.reg .pred p;\n\t" \
        "mbarrier.try_wait.parity.acquire.cta.shared::cta.b64 p, [%1], %2;\n\t" \
        "selp.b32 %0, 1, 0, p;\n\t}" : "=r"(_d) : "r"(_m), "r"(_p) : "memory"); \
    if (!_d) { asm volatile("{\n\t.reg .pred P1;\n\tWL_%=:\n\t" \
        "mbarrier.try_wait.parity.acquire.cta.shared::cta.b64 P1, [%0], %1, 0x989680;\n\t" \
        "@P1 bra.uni WD_%=;\n\tbra.uni WL_%=;\n\tWD_%=:\n\t}" \
        :: "r"(_m), "r"(_p) : "memory"); } \
} while (0)
#define BULK_CP(dst, src, sz, mb) \
    asm volatile("cp.async.bulk.shared::cluster.global.mbarrier::complete_tx::bytes [%0], [%1], %2, [%3];" \
        :: "r"(dst), "l"(src), "r"(sz), "r"(mb) : "memory")

#define TC_ALLOC(sa, n)   asm volatile("tcgen05.alloc.cta_group::1.sync.aligned.shared::cta.b32 [%0], %1;" :: "r"(sa), "r"(n) : "memory")
#define TC_RELINQ()       asm volatile("tcgen05.relinquish_alloc_permit.cta_group::1.sync.aligned;")
#define TC_DEALLOC(t, n)  asm volatile("tcgen05.dealloc.cta_group::1.sync.aligned.b32 %0, %1;" :: "r"(t), "r"(n))
#define TC_COMMIT(mb)     asm volatile("tcgen05.commit.cta_group::1.mbarrier::arrive::one.shared::cluster.b64 [%0];" :: "r"(mb) : "memory")
#define TC_FENCE_AFTER()  asm volatile("tcgen05.fence::after_thread_sync;" ::: "memory")
#define TC_FENCE_BEFORE() asm volatile("tcgen05.fence::before_thread_sync;" ::: "memory")
#define TC_WAIT_LD()      asm volatile("tcgen05.wait::ld.sync.aligned;" ::: "memory")
#define TC_WAIT_ST()      asm volatile("tcgen05.wait::st.sync.aligned;" ::: "memory")
#define FENCE_ASYNC()     asm volatile("fence.proxy.async.shared::cta;" ::: "memory")

#define TC_LD_X32(r, ta) \
    asm volatile("tcgen05.ld.sync.aligned.32x32b.x32.b32 " \
        "{%0, %1, %2, %3, %4, %5, %6, %7, %8, %9, %10, %11, %12, %13, %14, %15, " \
        " %16, %17, %18, %19, %20, %21, %22, %23, %24, %25, %26, %27, %28, %29, %30, %31}, [%32];" \
        : "=r"((r)[0]), "=r"((r)[1]), "=r"((r)[2]), "=r"((r)[3]), \
          "=r"((r)[4]), "=r"((r)[5]), "=r"((r)[6]), "=r"((r)[7]), \
          "=r"((r)[8]), "=r"((r)[9]), "=r"((r)[10]), "=r"((r)[11]), \
          "=r"((r)[12]), "=r"((r)[13]), "=r"((r)[14]), "=r"((r)[15]), \
          "=r"((r)[16]), "=r"((r)[17]), "=r"((r)[18]), "=r"((r)[19]), \
          "=r"((r)[20]), "=r"((r)[21]), "=r"((r)[22]), "=r"((r)[23]), \
          "=r"((r)[24]), "=r"((r)[25]), "=r"((r)[26]), "=r"((r)[27]), \
          "=r"((r)[28]), "=r"((r)[29]), "=r"((r)[30]), "=r"((r)[31]) \
        : "r"(ta))

#define TC_ST_X32(ta, r) \
    asm volatile("tcgen05.st.sync.aligned.32x32b.x32.b32 [%0], " \
        "{%1, %2, %3, %4, %5, %6, %7, %8, %9, %10, %11, %12, %13, %14, %15, %16, " \
        " %17, %18, %19, %20, %21, %22, %23, %24, %25, %26, %27, %28, %29, %30, %31, %32};" \
        :: "r"(ta), \
           "r"((r)[0]), "r"((r)[1]), "r"((r)[2]), "r"((r)[3]), \
           "r"((r)[4]), "r"((r)[5]), "r"((r)[6]), "r"((r)[7]), \
           "r"((r)[8]), "r"((r)[9]), "r"((r)[10]), "r"((r)[11]), \
           "r"((r)[12]), "r"((r)[13]), "r"((r)[14]), "r"((r)[15]), \
           "r"((r)[16]), "r"((r)[17]), "r"((r)[18]), "r"((r)[19]), \
           "r"((r)[20]), "r"((r)[21]), "r"((r)[22]), "r"((r)[23]), \
           "r"((r)[24]), "r"((r)[25]), "r"((r)[26]), "r"((r)[27]), \
           "r"((r)[28]), "r"((r)[29]), "r"((r)[30]), "r"((r)[31]) \
        : "memory")

#define TC_MMA_TF32(dt, ad, bd, id, en) do { \
    uint32_t _e = (en) ? 1u : 0u; \
    asm volatile("{\n\t.reg .pred p;\n\tsetp.ne.u32 p, %5, 0;\n\t" \
        "tcgen05.mma.cta_group::1.kind::tf32 [%0], %1, %2, %3, {%4, %4, %4, %4}, p;\n\t}" \
        :: "r"(dt), "l"(ad), "l"(bd), "r"(id), "r"(0u), "r"(_e) : "memory"); \
} while (0)

#define TC_MMA_TF32_TS(dt, at, bd, id, en) do { \
    uint32_t _e = (en) ? 1u : 0u; \
    asm volatile("{\n\t.reg .pred p;\n\tsetp.ne.u32 p, %5, 0;\n\t" \
        "tcgen05.mma.cta_group::1.kind::tf32 [%0], [%1], %2, %3, {%4, %4, %4, %4}, p;\n\t}" \
        :: "r"(dt), "r"(at), "l"(bd), "r"(id), "r"(0u), "r"(_e) : "memory"); \
} while (0)

__device__ __forceinline__ uint64_t make_desc(uint32_t addr) {
    return ((uint64_t)2 << 61) | ((uint64_t)1 << 46) | ((uint64_t)64 << 32) |
           ((uint64_t)1 << 16) | (uint64_t)((addr >> 4) & 0x3FFF);
}
#define IDESC_G   ((1u << 4) | (2u << 7) | (2u << 10) | (32u << 17) | (8u << 24))  // M128 N256
#define IDESC_128 ((1u << 4) | (2u << 7) | (2u << 10) | (16u << 17) | (8u << 24))  // M128 N128
#define IDESC_PV  ((1u << 4) | (2u << 7) | (2u << 10) | (8u  << 17) | (8u << 24))  // M128 N64
#endif // HAS_TC

// ---------------- weight pre-swizzle -------------------------------------------
__global__ __launch_bounds__(256)
void prep_all(const float* __restrict__ Wq, const float* __restrict__ Wk,
              const float* __restrict__ Wv, const float* __restrict__ Wo,
              const float* __restrict__ W1, const float* __restrict__ W2,
              float* __restrict__ wqkvt, float* __restrict__ wot,
              float* __restrict__ w1t, float* __restrict__ w2t)
{
    int id = blockIdx.x;
    const float* src; float* dst; int Kd, Nd, lb;
    if      (id < 1024) { src = Wq; dst = wqkvt;            Kd = 512;  Nd = 512;  lb = id; }
    else if (id < 2048) { src = Wk; dst = wqkvt + 512*512;  Kd = 512;  Nd = 512;  lb = id - 1024; }
    else if (id < 3072) { src = Wv; dst = wqkvt + 2*512*512;Kd = 512;  Nd = 512;  lb = id - 2048; }
    else if (id < 4096) { src = Wo; dst = wot;              Kd = 512;  Nd = 512;  lb = id - 3072; }
    else if (id < 8192) { src = W1; dst = w1t;              Kd = 512;  Nd = 2048; lb = id - 4096; }
    else                { src = W2; dst = w2t;              Kd = 2048; Nd = 512;  lb = id - 8192; }
    int e = lb * 256 + threadIdx.x;
    int k = e / Nd, n = e % Nd;
    float v = src[e];
    int NC = Kd >> 5;
    int blk = (n >> 8) * NC + (k >> 5);
    int off = (n & 255) * 128 + (k & 31) * 4;
    int sw = off ^ ((off >> 3) & 0x70);
    *(float*)((char*)(dst + (size_t)blk * 8192) + sw) = v;
}

// ---------------- x row-major -> A-swizzled ------------------------------------
__global__ __launch_bounds__(256)
void swz_a(const float* __restrict__ src, float* __restrict__ dst)
{
    int idx = blockIdx.x * 256 + threadIdx.x;
    int e = idx * 4;
    int m = e >> 9, k = e & 511;
    float4 v = *(const float4*)(src + (size_t)e);
    int blk = (m >> 7) * 16 + (k >> 5);
    *(float4*)(dst + (size_t)blk * 4096 + swz_fi(m & 127, k & 31)) = v;
}

// ---------------- GEMM ----------------------------------------------------------
#define GEMM_SMEM_S2  98304
#define GEMM_SMEM_S3  147456
template<int MODE, int STAGES>
__global__ __launch_bounds__(256, 2)
void gemmT(const float* __restrict__ A, const float* __restrict__ Wt,
           const float* __restrict__ bias0, const float* __restrict__ bias1,
           const float* __restrict__ bias2, const float* __restrict__ resid,
           float* __restrict__ out0, float* __restrict__ out1, float* __restrict__ out2,
           int N, int K)
{
    extern __shared__ __align__(1024) float sm[];
    const int tid = threadIdx.x, wid = tid >> 5, lane = tid & 31;
    const int n0 = blockIdx.x * 256, m0 = blockIdx.y * 128;
    const int NC = K >> 5;

#if HAS_TC
    __shared__ uint32_t s_tptr;
    __shared__ unsigned long long s_mb[6];
    const uint32_t smb = smem_u32(sm);
    const uint32_t BOF = STAGES * 16384u;

    if (wid == 0) { TC_ALLOC(smem_u32(&s_tptr), 256); TC_RELINQ(); }
    if (tid == 0) {
        #pragma unroll
        for (int i = 0; i < 6; ++i) MBAR_INIT(smem_u32(&s_mb[i]), 1);
    }
    __syncthreads();
    const uint32_t tmem = s_tptr;
    uint32_t mbB[3] = {smem_u32(&s_mb[0]), smem_u32(&s_mb[1]), smem_u32(&s_mb[2])};
    uint32_t mbM[3] = {smem_u32(&s_mb[3]), smem_u32(&s_mb[4]), smem_u32(&s_mb[5])};

    if (tid == 0) {
        int cB[3] = {0, 0, 0}, cM[3] = {0, 0, 0};
        const size_t ablk = (size_t)blockIdx.y * NC;
        const size_t bblk = (size_t)blockIdx.x * NC;
        #pragma unroll
        for (int s = 0; s < STAGES; ++s) {
            MBAR_EXPECT_TX(mbB[s], 49152u);
            BULK_CP(smb + s * 16384, (const void*)(A + (ablk + s) * 4096), 16384u, mbB[s]);
            BULK_CP(smb + BOF + s * 32768, (const void*)(Wt + (bblk + s) * 8192), 32768u, mbB[s]);
        }
        for (int s = 0; s < NC; ++s) {
            const int buf = s % STAGES;
            MBAR_WAIT(mbB[buf], cB[buf] & 1); cB[buf]++;
            uint64_t ad = make_desc(smb + buf * 16384);
            uint64_t bd = make_desc(smb + BOF + buf * 32768);
            #pragma unroll
            for (int s2 = 0; s2 < 4; ++s2)
                TC_MMA_TF32(tmem, ad + 2 * s2, bd + 2 * s2, IDESC_G, (s > 0) || (s2 > 0));
            TC_COMMIT(mbM[buf]);
            if (s + STAGES < NC) {
                MBAR_WAIT(mbM[buf], cM[buf] & 1); cM[buf]++;
                MBAR_EXPECT_TX(mbB[buf], 49152u);
                BULK_CP(smb + buf * 16384, (const void*)(A + (ablk + s + STAGES) * 4096),
                        16384u, mbB[buf]);
                BULK_CP(smb + BOF + buf * 32768, (const void*)(Wt + (bblk + s + STAGES) * 8192),
                        32768u, mbB[buf]);
            }
        }
        #pragma unroll
        for (int b2 = 0; b2 < STAGES; ++b2) {
            int cnt = (NC - b2 + STAGES - 1) / STAGES;
            if (cnt > cM[b2]) MBAR_WAIT(mbM[b2], (cnt - 1) & 1);
        }
    }
    __syncthreads();
    TC_FENCE_AFTER();

    const int sp = wid & 3, chh = wid >> 2;
    for (int cg = 0; cg < 4; ++cg) {
        uint32_t r[32];
        TC_LD_X32(r, tmem + cg * 64 + chh * 32);
        TC_WAIT_LD();
        const int row = sp * 32 + lane;
        #pragma unroll
        for (int j = 0; j < 32; ++j) sm[row * 65 + chh * 32 + j] = __uint_as_float(r[j]);
        __syncthreads();

        const int nb = n0 + cg * 64;
        if (MODE == 0) {
            const int which = nb >> 9;
            const int hh = (nb >> 6) & 7;
            const int b_ = m0 >> 12;
            const int tile = (m0 & 4095) >> 7;
            const size_t tbase = ((size_t)(b_ * NHEAD + hh) * (SEQ / 128) + tile) * 8192;
            if (which < 2) {
                const int r2 = tid & 127, sel = tid >> 7;
                const float* bp = which ? bias1 : bias0;
                float* outw = which ? out1 : out0;
                const float scale = which ? 1.f : 0.125f;
                const float* src = &sm[r2 * 65 + sel * 32];
                float vv[32];
                #pragma unroll
                for (int j = 0; j < 32; ++j)
                    vv[j] = (src[j] + bp[(nb & 511) + sel * 32 + j]) * scale;
                float* dstb = outw + tbase + sel * 4096 + r2 * 32;
                #pragma unroll
                for (int g = 0; g < 8; ++g)
                    *(float4*)(dstb + ((g ^ (r2 & 7)) << 2)) =
                        make_float4(vv[g * 4], vv[g * 4 + 1], vv[g * 4 + 2], vv[g * 4 + 3]);
            } else {
                const int dloc = tid & 63, kg = tid >> 6;
                const float bia = bias2[(nb & 511) + dloc];
                float vv[32];
                #pragma unroll
                for (int i = 0; i < 32; ++i)
                    vv[i] = sm[(kg * 32 + i) * 65 + dloc] + bia;
                float* dstb = out2 + tbase + kg * 2048 + dloc * 32;
                #pragma unroll
                for (int g = 0; g < 8; ++g)
                    *(float4*)(dstb + ((g ^ (dloc & 7)) << 2)) =
                        make_float4(vv[g * 4], vv[g * 4 + 1], vv[g * 4 + 2], vv[g * 4 + 3]);
            }
        } else if (MODE == 2) {
            const int r2 = tid & 127, sel = tid >> 7;
            const int m = m0 + r2;
            const int n = nb + sel * 32;
            const float* src = &sm[r2 * 65 + sel * 32];
            float* dst = out0 + (size_t)m * N + n;
            const float* rs = resid + (size_t)m * N + n;
            #pragma unroll
            for (int g = 0; g < 8; ++g) {
                float4 b4 = *(const float4*)(bias0 + n + g * 4);
                float4 r4 = *(const float4*)(rs + g * 4);
                *(float4*)(dst + g * 4) = make_float4(
                    src[g * 4 + 0] + b4.x + r4.x, src[g * 4 + 1] + b4.y + r4.y,
                    src[g * 4 + 2] + b4.z + r4.z, src[g * 4 + 3] + b4.w + r4.w);
            }
        } else {
            const int r2 = tid & 127, sel = tid >> 7;
            const int n = nb + sel * 32;
            const float* src = &sm[r2 * 65 + sel * 32];
            float vv[32];
            #pragma unroll
            for (int j = 0; j < 32; ++j) vv[j] = gelu_f(src[j] + bias0[n + j]);
            float* dstb = out0 + ((size_t)(m0 >> 7) * (DFF / 32) + (n >> 5)) * 4096 + r2 * 32;
            #pragma unroll
            for (int g = 0; g < 8; ++g)
                *(float4*)(dstb + ((g ^ (r2 & 7)) << 2)) =
                    make_float4(vv[g * 4], vv[g * 4 + 1], vv[g * 4 + 2], vv[g * 4 + 3]);
        }
        __syncthreads();
    }
    if (wid == 0) TC_DEALLOC(tmem, 256);

#else
    for (int e = tid; e < 128 * 256; e += 256) {
        int mr = e & 127, nc = e >> 7;
        int m = m0 + mr, n = n0 + nc;
        float acc = 0.f;
        for (int k = 0; k < K; ++k) {
            float a = A[((size_t)(m >> 7) * NC + (k >> 5)) * 4096 + swz_fi(m & 127, k & 31)];
            acc += a * ld_swz(Wt, NC, n, k);
        }
        if (MODE == 0) {
            int which = n >> 9, hh = (n >> 6) & 7;
            int b_ = m >> 12, l = m & (SEQ - 1);
            size_t tbase = ((size_t)(b_ * NHEAD + hh) * (SEQ / 128) + (l >> 7)) * 8192;
            if (which < 2) {
                const float* bp = which ? bias1 : bias0;
                float* outw = which ? out1 : out0;
                float val = (acc + bp[n & 511]) * (which ? 1.f : 0.125f);
                outw[tbase + ((n >> 5) & 1) * 4096 + swz_fi(l & 127, n & 31)] = val;
            } else {
                out2[tbase + ((l & 127) >> 5) * 2048 + swz_fi(n & 63, l & 31)] = acc + bias2[n & 511];
            }
        } else if (MODE == 2) {
            out0[(size_t)m * N + n] = acc + bias0[n] + resid[(size_t)m * N + n];
        } else {
            out0[((size_t)(m >> 7) * (DFF / 32) + (n >> 5)) * 4096 + swz_fi(m & 127, n & 31)] =
                gelu_f(acc + bias0[n]);
        }
    }
#endif
}

// ---------------- attention: BQ=128, Q in TMEM, 2 CTAs/SM -----------------------
#define ATTN_SMEM 101376

__global__ __launch_bounds__(256, 2)
void attn_k(const float* __restrict__ q, const float* __restrict__ k,
            const float* __restrict__ v, const int* __restrict__ mask,
            float* __restrict__ ctx)
{
    extern __shared__ __align__(1024) float sm[];
    const int qt = blockIdx.x, h = blockIdx.y, b = blockIdx.z;
    const int tid = threadIdx.x;
    const size_t tb = (size_t)(b * NHEAD + h) * (SEQ / 128);

#if HAS_TC
    float* Ks  = sm;                  // 2 x 8192 (slot0 stages Q first)
    float* Vs  = sm + 16384;          // 8192
    float* lpart = sm + 24576;        // 256
    float* Msm = sm + 24832;          // [4][128] mask as 1.0f / 0.0f

    __shared__ uint32_t s_tptr;
    __shared__ unsigned long long s_mb[6];   // Q K0 K1 V S O
    const int wid = tid >> 5, lane = tid & 31;
    const int sp = wid & 3, chh = wid >> 2;
    const int NT = SEQ / 128;

    if (wid == 0) { TC_ALLOC(smem_u32(&s_tptr), 256); TC_RELINQ(); }
    if (tid == 0) {
        #pragma unroll
        for (int i = 0; i < 6; ++i) MBAR_INIT(smem_u32(&s_mb[i]), 1);
    }
    __syncthreads();
    const uint32_t tmem = s_tptr;
    const uint32_t mbQ = smem_u32(&s_mb[0]);
    uint32_t mbK[2] = {smem_u32(&s_mb[1]), smem_u32(&s_mb[2])};
    const uint32_t mbV = smem_u32(&s_mb[3]);
    const uint32_t mbS = smem_u32(&s_mb[4]);
    const uint32_t mbO = smem_u32(&s_mb[5]);
    const uint32_t S_T = tmem, O_T = tmem + 128, Q_T = tmem + 192;

    #define ISSUE_QK(kbuf) do { \
        uint64_t kd = make_desc(smem_u32(Ks + (kbuf) * 8192)); \
        _Pragma("unroll") \
        for (int c = 0; c < 2; ++c) \
            _Pragma("unroll") \
            for (int s = 0; s < 4; ++s) \
                TC_MMA_TF32_TS(S_T, Q_T + (c * 4 + s) * 8, kd + c * 1024 + 2 * s, \
                               IDESC_128, (c > 0) || (s > 0)); \
        TC_COMMIT(mbS); \
    } while (0)

    #define ISSUE_PV(t) do { \
        _Pragma("unroll") \
        for (int cc = 0; cc < 4; ++cc) { \
            uint64_t vd = make_desc(smem_u32(Vs + cc * 2048)); \
            _Pragma("unroll") \
            for (int s = 0; s < 4; ++s) \
                TC_MMA_TF32_TS(O_T, S_T + cc * 32 + s * 8, vd + 2 * s, IDESC_PV, \
                               ((t) > 0) || (cc > 0) || (s > 0)); \
        } \
        TC_COMMIT(mbO); \
    } while (0)

    // softmax with float-multiplier masking (select-free: FMNMX + MUFU + 2xFMUL)
    #define SOFTMAX(tslot, lsum) do { \
        uint32_t ra[32], rb[32]; \
        TC_LD_X32(ra, S_T + chh * 64); \
        TC_WAIT_LD(); \
        TC_LD_X32(rb, S_T + chh * 64 + 32); \
        const float* mrow = &Msm[(tslot) * 128 + chh * 64]; \
        _Pragma("unroll") \
        for (int j = 0; j < 32; ++j) { \
            float s = __uint_as_float(ra[j]); \
            float p = __expf(fminf(s, 60.f)) * mrow[j]; \
            (lsum) += p; \
            ra[j] = __float_as_uint(p); \
        } \
        TC_WAIT_LD(); \
        TC_ST_X32(S_T + chh * 64, ra); \
        _Pragma("unroll") \
        for (int j = 0; j < 32; ++j) { \
            float s = __uint_as_float(rb[j]); \
            float p = __expf(fminf(s, 60.f)) * mrow[32 + j]; \
            (lsum) += p; \
            rb[j] = __float_as_uint(p); \
        } \
        TC_ST_X32(S_T + chh * 64 + 32, rb); \
        TC_WAIT_ST(); \
        TC_FENCE_BEFORE(); \
    } while (0)

    // ---- prologue: Q -> K-slot0, K(0) -> slot1, V(0) ----
    // K(j) slot: 1 - (j & 1)  (K0->1, K1->0, K2->1, ...)
    if (tid == 0) {
        MBAR_EXPECT_TX(mbQ, 32768u);
        BULK_CP(smem_u32(Ks), (const void*)(q + (tb + qt) * 8192), 32768u, mbQ);
        MBAR_EXPECT_TX(mbK[1], 32768u);
        BULK_CP(smem_u32(Ks + 8192), (const void*)(k + tb * 8192), 32768u, mbK[1]);
        MBAR_EXPECT_TX(mbV, 32768u);
        BULK_CP(smem_u32(Vs), (const void*)(v + tb * 8192), 32768u, mbV);
    }
    if (tid < 128) {
        Msm[tid] = mask[b * SEQ + tid] ? 1.f : 0.f;
        Msm[128 + tid] = mask[b * SEQ + 128 + tid] ? 1.f : 0.f;
    }
    MBAR_WAIT(mbQ, 0);
    if (wid < 4) {
        const int row = wid * 32 + lane;
        #pragma unroll
        for (int cchunk = 0; cchunk < 2; ++cchunk) {
            uint32_t qr[32];
            const float* base = Ks + cchunk * 4096 + row * 32;
            #pragma unroll
            for (int g = 0; g < 8; ++g) {
                float4 f = *(const float4*)(base + ((g ^ (row & 7)) << 2));
                qr[g * 4 + 0] = __float_as_uint(f.x);
                qr[g * 4 + 1] = __float_as_uint(f.y);
                qr[g * 4 + 2] = __float_as_uint(f.z);
                qr[g * 4 + 3] = __float_as_uint(f.w);
            }
            TC_ST_X32(Q_T + cchunk * 32, qr);
        }
        TC_WAIT_ST();
    }
    TC_FENCE_BEFORE();
    __syncthreads();

    int cK[2] = {0, 0}, cV = 0;
    if (tid == 0) {
        TC_FENCE_AFTER();
        MBAR_WAIT(mbK[1], 0); cK[1] = 1;
        ISSUE_QK(1);
        if (1 < NT) {
            MBAR_EXPECT_TX(mbK[0], 32768u);
            BULK_CP(smem_u32(Ks), (const void*)(k + (tb + 1) * 8192), 32768u, mbK[0]);
        }
    }

    float lsum = 0.f;

    for (int t = 0; t < NT; ++t) {
        MBAR_WAIT(mbS, t & 1);
        TC_FENCE_AFTER();
        SOFTMAX((t & 3), lsum);
        __syncthreads();
        if (tid == 0) {
            TC_FENCE_AFTER();
            MBAR_WAIT(mbV, cV & 1); cV++;
            ISSUE_PV(t);
            MBAR_WAIT(mbO, t & 1);
            if (t + 1 < NT) {
                MBAR_EXPECT_TX(mbV, 32768u);
                BULK_CP(smem_u32(Vs), (const void*)(v + (tb + t + 1) * 8192), 32768u, mbV);
                const int kb = t & 1;            // slot of K(t+1)
                MBAR_WAIT(mbK[kb], cK[kb] & 1); cK[kb]++;
                ISSUE_QK(kb);
                if (t + 2 < NT) {
                    const int kb2 = 1 - kb;      // slot of K(t+2)
                    MBAR_EXPECT_TX(mbK[kb2], 32768u);
                    BULK_CP(smem_u32(Ks + kb2 * 8192), (const void*)(k + (tb + t + 2) * 8192),
                            32768u, mbK[kb2]);
                }
            }
        }
        if (t + 2 < NT && tid < 128)
            Msm[((t + 2) & 3) * 128 + tid] = mask[b * SEQ + (t + 2) * 128 + tid] ? 1.f : 0.f;
        __syncthreads();
    }

    // ---- combine l, read O, normalize, store ctx (A-swizzled layout) ----
    const int rr = sp * 32 + lane;
    lpart[chh * 128 + rr] = lsum;
    __syncthreads();
    float linv = 1.f / (lpart[rr] + lpart[128 + rr]);

    TC_FENCE_AFTER();
    uint32_t ro[32];
    TC_LD_X32(ro, O_T + chh * 32);
    TC_WAIT_LD();
    float vv[32];
    #pragma unroll
    for (int j = 0; j < 32; ++j) vv[j] = __uint_as_float(ro[j]) * linv;
    float* dstb = ctx + ((size_t)(b * (SEQ / 128) + qt) * (D_EMBED / 32) + h * 2 + chh) * 4096
                      + rr * 32;
    #pragma unroll
    for (int g = 0; g < 8; ++g)
        *(float4*)(dstb + ((g ^ (rr & 7)) << 2)) =
            make_float4(vv[g * 4], vv[g * 4 + 1], vv[g * 4 + 2], vv[g * 4 + 3]);
    __syncthreads();
    if (wid == 0) TC_DEALLOC(tmem, 256);
    #undef ISSUE_QK
    #undef ISSUE_PV
    #undef SOFTMAX

#else
    // naive correct fallback (never runs on sm_103a HW)
    if (tid >= 128) return;
    const int rr = tid;
    const float* qb2 = q + (tb + qt) * 8192;
    float qv[64], o[64];
    #pragma unroll
    for (int d = 0; d < 64; ++d) {
        qv[d] = qb2[(d >> 5) * 4096 + swz_fi(rr, d & 31)];
        o[d] = 0.f;
    }
    float lsum = 0.f;
    for (int l = 0; l < SEQ; ++l) {
        int kt = l >> 7, r = l & 127;
        const float* kb2 = k + (tb + kt) * 8192;
        float s = 0.f;
        for (int d = 0; d < 64; ++d) s += qv[d] * kb2[(d >> 5) * 4096 + swz_fi(r, d & 31)];
        s = mask[b * SEQ + l] ? s : -1e9f;
        float p = __expf(fminf(s, 60.f));
        lsum += p;
        const float* vb2 = v + (tb + kt) * 8192;
        for (int d = 0; d < 64; ++d) o[d] += p * vb2[(r >> 5) * 2048 + swz_fi(d, r & 31)];
    }
    float linv = 1.f / lsum;
    for (int ch = 0; ch < 2; ++ch) {
        float* dstb = ctx + ((size_t)(b * (SEQ / 128) + qt) * (D_EMBED / 32) + h * 2 + ch) * 4096;
        for (int j = 0; j < 32; ++j)
            dstb[swz_fi(rr, j)] = o[ch * 32 + j] * linv;
    }
#endif
}

// ---------------- LayerNorm (optionally emits A-swizzled copy) ------------------
__global__ __launch_bounds__(128)
void ln_k(const float* __restrict__ in, const float* __restrict__ gam,
          const float* __restrict__ bet, float* __restrict__ out,
          float* __restrict__ out_aswz)
{
    const int row = blockIdx.x;
    const int tid = threadIdx.x;
    float4 vx = ((const float4*)(in + (size_t)row * D_EMBED))[tid];
    float s  = vx.x + vx.y + vx.z + vx.w;
    float ss = vx.x * vx.x + vx.y * vx.y + vx.z * vx.z + vx.w * vx.w;
    #pragma unroll
    for (int o = 16; o; o >>= 1) {
        s  += __shfl_xor_sync(0xffffffffu, s, o);
        ss += __shfl_xor_sync(0xffffffffu, ss, o);
    }
    __shared__ float sh[8];
    if ((tid & 31) == 0) { sh[tid >> 5] = s; sh[4 + (tid >> 5)] = ss; }
    __syncthreads();
    float S  = sh[0] + sh[1] + sh[2] + sh[3];
    float SS = sh[4] + sh[5] + sh[6] + sh[7];
    float mu   = S * (1.f / 512.f);
    float var  = SS * (1.f / 512.f) - mu * mu;
    float rstd = rsqrtf(var + 1e-5f);
    float4 g  = ((const float4*)gam)[tid];
    float4 bb = ((const float4*)bet)[tid];
    float4 o;
    o.x = (vx.x - mu) * rstd * g.x + bb.x;
    o.y = (vx.y - mu) * rstd * g.y + bb.y;
    o.z = (vx.z - mu) * rstd * g.z + bb.z;
    o.w = (vx.w - mu) * rstd * g.w + bb.w;
    ((float4*)(out + (size_t)row * D_EMBED))[tid] = o;
    if (out_aswz) {
        int kk = tid * 4;
        int blk = (row >> 7) * 16 + (kk >> 5);
        *(float4*)(out_aswz + (size_t)blk * 4096 + swz_fi(row & 127, kk & 31)) = o;
    }
}

// ---------------- launcher -------------------------------------------------------
extern "C" void kernel_launch(void* const* d_in, const int* in_sizes, int n_in,
                              void* d_out, int out_size)
{
    const float* x    = (const float*)d_in[0];
    const int*   mask = (const int*)  d_in[1];
    const float* Wq   = (const float*)d_in[2];
    const float* bq   = (const float*)d_in[3];
    const float* Wk   = (const float*)d_in[4];
    const float* bk   = (const float*)d_in[5];
    const float* Wv   = (const float*)d_in[6];
    const float* bv   = (const float*)d_in[7];
    const float* Wo   = (const float*)d_in[8];
    const float* bo   = (const float*)d_in[9];

    const float *ln1g, *ln1b, *ln2g, *ln2b, *W1, *b1, *W2, *b2;
    if (in_sizes[12] == D_EMBED * DFF) {
        ln1g = (const float*)d_in[10]; ln1b = (const float*)d_in[11];
        W1   = (const float*)d_in[12]; b1   = (const float*)d_in[13];
        W2   = (const float*)d_in[14]; b2   = (const float*)d_in[15];
        ln2g = (const float*)d_in[16]; ln2b = (const float*)d_in[17];
    } else {
        ln1g = (const float*)d_in[10]; ln1b = (const float*)d_in[11];
        ln2g = (const float*)d_in[12]; ln2b = (const float*)d_in[13];
        W1   = (const float*)d_in[14]; b1   = (const float*)d_in[15];
        W2   = (const float*)d_in[16]; b2   = (const float*)d_in[17];
    }

    float *q, *k, *v, *ctx, *res1, *h, *hs, *xs, *ff, *res2;
    float *wqkvt, *wot, *w1t, *w2t;
    cudaGetSymbolAddress((void**)&q,    g_q);
    cudaGetSymbolAddress((void**)&k,    g_k);
    cudaGetSymbolAddress((void**)&v,    g_v);
    cudaGetSymbolAddress((void**)&ctx,  g_ctx);
    cudaGetSymbolAddress((void**)&res1, g_res1);
    cudaGetSymbolAddress((void**)&h,    g_h);
    cudaGetSymbolAddress((void**)&hs,   g_hs);
    cudaGetSymbolAddress((void**)&xs,   g_xs);
    cudaGetSymbolAddress((void**)&ff,   g_ff);
    cudaGetSymbolAddress((void**)&res2, g_res2);
    cudaGetSymbolAddress((void**)&wqkvt, g_wqkvt);
    cudaGetSymbolAddress((void**)&wot,   g_wot);
    cudaGetSymbolAddress((void**)&w1t,   g_w1t);
    cudaGetSymbolAddress((void**)&w2t,   g_w2t);

    static bool attr_done = false;
    if (!attr_done) {
        cudaFuncSetAttribute(attn_k, cudaFuncAttributeMaxDynamicSharedMemorySize, ATTN_SMEM);
        cudaFuncSetAttribute((gemmT<0,2>), cudaFuncAttributeMaxDynamicSharedMemorySize, GEMM_SMEM_S2);
        cudaFuncSetAttribute((gemmT<3,2>), cudaFuncAttributeMaxDynamicSharedMemorySize, GEMM_SMEM_S2);
        cudaFuncSetAttribute((gemmT<2,3>), cudaFuncAttributeMaxDynamicSharedMemorySize, GEMM_SMEM_S3);
        attr_done = true;
    }

    prep_all<<<12288, 256>>>(Wq, Wk, Wv, Wo, W1, W2, wqkvt, wot, w1t, w2t);
    swz_a<<<4096, 256>>>(x, xs);

    gemmT<0,2><<<dim3(6, 64), 256, GEMM_SMEM_S2>>>(xs, wqkvt, bq, bk, bv, nullptr,
                                                   q, k, v, 3 * D_EMBED, D_EMBED);

    attn_k<<<dim3(SEQ / 128, NHEAD, BATCH), 256, ATTN_SMEM>>>(q, k, v, mask, ctx);

    gemmT<2,3><<<dim3(2, 64), 256, GEMM_SMEM_S3>>>(ctx, wot, bo, nullptr, nullptr, x,
                                                   res1, nullptr, nullptr, D_EMBED, D_EMBED);
    ln_k<<<NROWS, 128>>>(res1, ln1g, ln1b, h, hs);

    gemmT<3,2><<<dim3(8, 64), 256, GEMM_SMEM_S2>>>(hs, w1t, b1, nullptr, nullptr, nullptr,
                                                   ff, nullptr, nullptr, DFF, D_EMBED);
    gemmT<2,3><<<dim3(2, 64), 256, GEMM_SMEM_S3>>>(ff, w2t, b2, nullptr, nullptr, h,
                                                   res2, nullptr, nullptr, D_EMBED, DFF);
    ln_k<<<NROWS, 128>>>(res2, ln2g, ln2b, (float*)d_out, nullptr);
}